// round 5
// baseline (speedup 1.0000x reference)
#include <cuda_runtime.h>
#include <cstdint>

// Problem constants (GINClassifier: N=50000 nodes, d=128, 800000 edges, 40 classes)
#define NN 50000
#define EE 800000
#define DH 128
#define NCLS 40

// ---------------- scratch (static __device__ globals; no allocation) ----------------
__device__ __align__(16) float g_agg[NN * DH];        // aggregation output  (25.6 MB)
__device__ __align__(16) float g_h[NN * DH];          // layer activations   (25.6 MB)
__device__ __align__(16) float g_hidden[NN * 2 * DH]; // MLP hidden          (51.2 MB)
__device__ int g_cnt[NN];
__device__ int g_rowptr[NN + 1];
__device__ int g_cursor[NN];
__device__ int g_col[EE];
__device__ int g_is64;

// ---------------- dtype detection: int64 vs int32 edge_index ----------------
// Genuine little-endian int64 with values in [0,50000): every odd 32-bit word is 0.
__global__ void detect_dtype_kernel(const int* __restrict__ ei32, int n_words) {
    if (threadIdx.x == 0 && blockIdx.x == 0) {
        int all_zero = 1;
        for (int k = 0; k < 128; k++) {
            int idx = 2 * k + 1;
            if (idx < n_words && ei32[idx] != 0) { all_zero = 0; break; }
        }
        g_is64 = all_zero;
    }
}

// ---------------- CSR build ----------------
__global__ void zero_int_kernel(int* p, int n) {
    int i = blockIdx.x * blockDim.x + threadIdx.x;
    if (i < n) p[i] = 0;
}

__global__ void count_kernel(const void* __restrict__ ei, int E) {
    int e = blockIdx.x * blockDim.x + threadIdx.x;
    if (e >= E) return;
    int d;
    if (g_is64) d = (int)((const long long*)ei)[E + e];   // dst row
    else        d = ((const int*)ei)[E + e];
    atomicAdd(&g_cnt[d], 1);
}

__global__ void scan_kernel(int n) {
    __shared__ int s[1024];
    __shared__ int carry;
    if (threadIdx.x == 0) carry = 0;
    __syncthreads();
    for (int base = 0; base < n; base += 1024) {
        int i = base + (int)threadIdx.x;
        int v = (i < n) ? g_cnt[i] : 0;
        s[threadIdx.x] = v;
        __syncthreads();
        for (int off = 1; off < 1024; off <<= 1) {
            int t = (threadIdx.x >= (unsigned)off) ? s[threadIdx.x - off] : 0;
            __syncthreads();
            s[threadIdx.x] += t;
            __syncthreads();
        }
        int excl = carry + s[threadIdx.x] - v;   // exclusive prefix
        if (i < n) { g_rowptr[i] = excl; g_cursor[i] = excl; }
        __syncthreads();
        if (threadIdx.x == 0) carry += s[1023];
        __syncthreads();
    }
    if (threadIdx.x == 0) g_rowptr[n] = carry;
}

__global__ void fill_kernel(const void* __restrict__ ei, int E) {
    int e = blockIdx.x * blockDim.x + threadIdx.x;
    if (e >= E) return;
    int s, d;
    if (g_is64) {
        s = (int)((const long long*)ei)[e];
        d = (int)((const long long*)ei)[E + e];
    } else {
        s = ((const int*)ei)[e];
        d = ((const int*)ei)[E + e];
    }
    int pos = atomicAdd(&g_cursor[d], 1);
    g_col[pos] = s;
}

// ---------------- aggregation: out[i] = x[i] + sum_{e: dst=i} x[src[e]] ----------------
// one warp per node; d=128 floats = 32 lanes * float4
__global__ void agg_kernel(const float* __restrict__ x, float* __restrict__ out, int M) {
    int node = blockIdx.x * (blockDim.x >> 5) + (threadIdx.x >> 5);
    if (node >= M) return;
    int lane = threadIdx.x & 31;
    const float4* x4 = (const float4*)x;
    float4* out4 = (float4*)out;
    size_t base = (size_t)node * 32 + lane;
    float4 acc = x4[base];
    int e = g_rowptr[node];
    int end = g_rowptr[node + 1];
    // batch 4 gathers per iteration for MLP (hides L2 latency)
    for (; e + 4 <= end; e += 4) {
        int s0 = g_col[e], s1 = g_col[e + 1], s2 = g_col[e + 2], s3 = g_col[e + 3];
        float4 v0 = __ldg(&x4[(size_t)s0 * 32 + lane]);
        float4 v1 = __ldg(&x4[(size_t)s1 * 32 + lane]);
        float4 v2 = __ldg(&x4[(size_t)s2 * 32 + lane]);
        float4 v3 = __ldg(&x4[(size_t)s3 * 32 + lane]);
        acc.x += (v0.x + v1.x) + (v2.x + v3.x);
        acc.y += (v0.y + v1.y) + (v2.y + v3.y);
        acc.z += (v0.z + v1.z) + (v2.z + v3.z);
        acc.w += (v0.w + v1.w) + (v2.w + v3.w);
    }
    for (; e < end; e++) {
        int s = g_col[e];
        float4 v = __ldg(&x4[(size_t)s * 32 + lane]);
        acc.x += v.x; acc.y += v.y; acc.z += v.z; acc.w += v.w;
    }
    out4[base] = acc;
}

// ---------------- SGEMM: C[M,N] = relu?(A[M,K] @ B[K,N] + bias) ----------------
// BM=128 BN=128 BK=8, 256 threads, 8x8 microtile. N must be a multiple of 128.
#define BM 128
#define BN 128
#define BK 8
__global__ __launch_bounds__(256) void sgemm_kernel(
    const float* __restrict__ A, const float* __restrict__ B,
    const float* __restrict__ bias, float* __restrict__ C,
    int M, int N, int K, int relu)
{
    __shared__ __align__(16) float As[BK * BM];
    __shared__ __align__(16) float Bs[BK * BN];

    int tid = threadIdx.x;
    int block_row = blockIdx.y * BM;
    int block_col = blockIdx.x * BN;

    int a_row = tid >> 1;            // 0..127
    int a_col = (tid & 1) * 4;       // 0 or 4
    int b_row = tid >> 5;            // 0..7
    int b_col = (tid & 31) * 4;      // 0..124

    int tr = tid >> 4;               // 0..15
    int tc = tid & 15;               // 0..15
    int m0 = tr * 8;
    int n0 = tc * 8;

    // hoisted global pointers (incremented per K-tile; no per-iter IMAD chains)
    int gr = block_row + a_row;
    bool a_valid = gr < M;
    const float* a_ptr = A + (size_t)(a_valid ? gr : 0) * K + a_col;
    const float* b_ptr = B + (size_t)b_row * N + block_col + b_col;

    float acc[8][8];
#pragma unroll
    for (int i = 0; i < 8; i++)
#pragma unroll
        for (int j = 0; j < 8; j++) acc[i][j] = 0.0f;

    for (int k0 = 0; k0 < K; k0 += BK) {
        float4 av = a_valid ? *(const float4*)a_ptr
                            : make_float4(0.f, 0.f, 0.f, 0.f);
        a_ptr += BK;
        As[(a_col + 0) * BM + a_row] = av.x;
        As[(a_col + 1) * BM + a_row] = av.y;
        As[(a_col + 2) * BM + a_row] = av.z;
        As[(a_col + 3) * BM + a_row] = av.w;

        float4 bv = *(const float4*)b_ptr;
        b_ptr += (size_t)BK * N;
        *(float4*)&Bs[b_row * BN + b_col] = bv;
        __syncthreads();

#pragma unroll
        for (int k = 0; k < BK; k++) {
            float4 a0 = *(const float4*)&As[k * BM + m0];
            float4 a1 = *(const float4*)&As[k * BM + m0 + 4];
            float4 b0 = *(const float4*)&Bs[k * BN + n0];
            float4 b1 = *(const float4*)&Bs[k * BN + n0 + 4];
            float a[8] = {a0.x, a0.y, a0.z, a0.w, a1.x, a1.y, a1.z, a1.w};
            float b[8] = {b0.x, b0.y, b0.z, b0.w, b1.x, b1.y, b1.z, b1.w};
#pragma unroll
            for (int i = 0; i < 8; i++)
#pragma unroll
                for (int j = 0; j < 8; j++)
                    acc[i][j] += a[i] * b[j];
        }
        __syncthreads();
    }

#pragma unroll
    for (int i = 0; i < 8; i++) {
        int grr = block_row + m0 + i;
        if (grr >= M) continue;
#pragma unroll
        for (int j = 0; j < 8; j += 4) {
            int gc = block_col + n0 + j;
            float4 v;
            v.x = acc[i][j + 0] + bias[gc + 0];
            v.y = acc[i][j + 1] + bias[gc + 1];
            v.z = acc[i][j + 2] + bias[gc + 2];
            v.w = acc[i][j + 3] + bias[gc + 3];
            if (relu) {
                v.x = fmaxf(v.x, 0.f); v.y = fmaxf(v.y, 0.f);
                v.z = fmaxf(v.z, 0.f); v.w = fmaxf(v.w, 0.f);
            }
            *(float4*)&C[(size_t)grr * N + gc] = v;
        }
    }
}

// ---------------- classifier: out[M,40] = A[M,128] @ W[128,40] + b ----------------
__global__ __launch_bounds__(256) void fc40_kernel(
    const float* __restrict__ A, const float* __restrict__ W,
    const float* __restrict__ bias, float* __restrict__ out, int M)
{
    __shared__ float Ws[DH * NCLS];
    for (int i = threadIdx.x; i < DH * NCLS; i += blockDim.x) Ws[i] = W[i];
    __syncthreads();

    int row = blockIdx.x * blockDim.x + threadIdx.x;
    if (row >= M) return;

    float acc[NCLS];
#pragma unroll
    for (int j = 0; j < NCLS; j++) acc[j] = bias[j];

    const float4* __restrict__ a4 = (const float4*)(A + (size_t)row * DH);
#pragma unroll 8
    for (int kc = 0; kc < DH / 4; kc++) {
        float4 av = a4[kc];
        int k = kc * 4;
        const float* w0 = &Ws[(k + 0) * NCLS];
        const float* w1 = &Ws[(k + 1) * NCLS];
        const float* w2 = &Ws[(k + 2) * NCLS];
        const float* w3 = &Ws[(k + 3) * NCLS];
#pragma unroll
        for (int j = 0; j < NCLS; j++)
            acc[j] += av.x * w0[j] + av.y * w1[j] + av.z * w2[j] + av.w * w3[j];
    }
    float* o = out + (size_t)row * NCLS;
#pragma unroll
    for (int j = 0; j < NCLS; j++) o[j] = acc[j];
}

// ---------------- launch ----------------
extern "C" void kernel_launch(void* const* d_in, const int* in_sizes, int n_in,
                              void* d_out, int out_size)
{
    const float* x    = (const float*)d_in[0];
    const void*  ei   = d_in[1];
    const float* W11  = (const float*)d_in[2];
    const float* b11  = (const float*)d_in[3];
    const float* W12  = (const float*)d_in[4];
    const float* b12  = (const float*)d_in[5];
    const float* W21  = (const float*)d_in[6];
    const float* b21  = (const float*)d_in[7];
    const float* W22  = (const float*)d_in[8];
    const float* b22  = (const float*)d_in[9];
    const float* Wfc  = (const float*)d_in[10];
    const float* bfc  = (const float*)d_in[11];

    int M = in_sizes[0] / DH;      // 50000
    int E = in_sizes[1] / 2;       // 800000

    float *p_agg, *p_h, *p_hidden;
    cudaGetSymbolAddress((void**)&p_agg, g_agg);
    cudaGetSymbolAddress((void**)&p_h, g_h);
    cudaGetSymbolAddress((void**)&p_hidden, g_hidden);
    int* p_cnt;
    cudaGetSymbolAddress((void**)&p_cnt, g_cnt);

    // dtype detection (int64 vs int32 edge_index)
    detect_dtype_kernel<<<1, 32>>>((const int*)ei, 2 * E);

    // CSR build (reused by both aggregations)
    zero_int_kernel<<<(M + 255) / 256, 256>>>(p_cnt, M);
    count_kernel<<<(E + 255) / 256, 256>>>(ei, E);
    scan_kernel<<<1, 1024>>>(M);
    fill_kernel<<<(E + 255) / 256, 256>>>(ei, E);

    int agg_blocks = (M + 7) / 8;  // 8 warps per block
    dim3 g1(2, (M + BM - 1) / BM); // N=256
    dim3 g2(1, (M + BM - 1) / BM); // N=128

    // Layer 1
    agg_kernel<<<agg_blocks, 256>>>(x, p_agg, M);
    sgemm_kernel<<<g1, 256>>>(p_agg, W11, b11, p_hidden, M, 2 * DH, DH, 1);
    sgemm_kernel<<<g2, 256>>>(p_hidden, W12, b12, p_h, M, DH, 2 * DH, 1);

    // Layer 2
    agg_kernel<<<agg_blocks, 256>>>(p_h, p_agg, M);
    sgemm_kernel<<<g1, 256>>>(p_agg, W21, b21, p_hidden, M, 2 * DH, DH, 1);
    sgemm_kernel<<<g2, 256>>>(p_hidden, W22, b22, p_h, M, DH, 2 * DH, 1);

    // Classifier
    fc40_kernel<<<(M + 255) / 256, 256>>>(p_h, Wfc, bfc, (float*)d_out, M);
}

// round 6
// speedup vs baseline: 1.1699x; 1.1699x over previous
#include <cuda_runtime.h>
#include <cstdint>

#define NN 50000
#define EE 800000
#define DH 128
#define NCLS 40

// ---------------- scratch ----------------
__device__ __align__(16) float g_agg[NN * DH];
__device__ __align__(16) float g_h[NN * DH];
__device__ __align__(16) float g_hidden[NN * 2 * DH];
__device__ int g_cnt[NN];
__device__ int g_rowptr[NN];     // segment start
__device__ int g_cursor[NN];     // fill cursor; after fill == segment end
__device__ int g_col[EE];
__device__ int g_total;
__device__ int g_is64;

// ---------------- dtype detection ----------------
__global__ void detect_dtype_kernel(const int* __restrict__ ei32, int n_words) {
    if (threadIdx.x == 0 && blockIdx.x == 0) {
        int all_zero = 1;
        for (int k = 0; k < 128; k++) {
            int idx = 2 * k + 1;
            if (idx < n_words && ei32[idx] != 0) { all_zero = 0; break; }
        }
        g_is64 = all_zero;
    }
}

// ---------------- CSR build (scan-free) ----------------
__global__ void zero_int_kernel(int* p, int n) {
    int i = blockIdx.x * blockDim.x + threadIdx.x;
    if (i < n) p[i] = 0;
    if (i == 0) g_total = 0;
}

__global__ void count_kernel(const void* __restrict__ ei, int E) {
    int e = blockIdx.x * blockDim.x + threadIdx.x;
    if (e >= E) return;
    int d;
    if (g_is64) d = (int)((const long long*)ei)[E + e];
    else        d = ((const int*)ei)[E + e];
    atomicAdd(&g_cnt[d], 1);
}

// parallel segment reservation: ordering of segments is irrelevant for a gather-sum
__global__ void reserve_kernel(int n) {
    int i = blockIdx.x * blockDim.x + threadIdx.x;
    if (i >= n) return;
    int c = g_cnt[i];
    int s = atomicAdd(&g_total, c);
    g_rowptr[i] = s;
    g_cursor[i] = s;
}

__global__ void fill_kernel(const void* __restrict__ ei, int E) {
    int e = blockIdx.x * blockDim.x + threadIdx.x;
    if (e >= E) return;
    int s, d;
    if (g_is64) {
        s = (int)((const long long*)ei)[e];
        d = (int)((const long long*)ei)[E + e];
    } else {
        s = ((const int*)ei)[e];
        d = ((const int*)ei)[E + e];
    }
    int pos = atomicAdd(&g_cursor[d], 1);
    g_col[pos] = s;
}

// ---------------- aggregation ----------------
__global__ void agg_kernel(const float* __restrict__ x, float* __restrict__ out, int M) {
    int node = blockIdx.x * (blockDim.x >> 5) + (threadIdx.x >> 5);
    if (node >= M) return;
    int lane = threadIdx.x & 31;
    const float4* x4 = (const float4*)x;
    float4* out4 = (float4*)out;
    size_t base = (size_t)node * 32 + lane;
    float4 acc = x4[base];
    int e = g_rowptr[node];
    int end = g_cursor[node];   // after fill: start + cnt
    for (; e + 4 <= end; e += 4) {
        int s0 = g_col[e], s1 = g_col[e + 1], s2 = g_col[e + 2], s3 = g_col[e + 3];
        float4 v0 = __ldg(&x4[(size_t)s0 * 32 + lane]);
        float4 v1 = __ldg(&x4[(size_t)s1 * 32 + lane]);
        float4 v2 = __ldg(&x4[(size_t)s2 * 32 + lane]);
        float4 v3 = __ldg(&x4[(size_t)s3 * 32 + lane]);
        acc.x += (v0.x + v1.x) + (v2.x + v3.x);
        acc.y += (v0.y + v1.y) + (v2.y + v3.y);
        acc.z += (v0.z + v1.z) + (v2.z + v3.z);
        acc.w += (v0.w + v1.w) + (v2.w + v3.w);
    }
    for (; e < end; e++) {
        int s = g_col[e];
        float4 v = __ldg(&x4[(size_t)s * 32 + lane]);
        acc.x += v.x; acc.y += v.y; acc.z += v.z; acc.w += v.w;
    }
    out4[base] = acc;
}

// ---------------- 3xTF32 tensor-core GEMM ----------------
// C[M,N] = relu?(A[M,K] @ B[K,N] + bias).  N % 128 == 0, K % 16 == 0.
// Block: 128x128x16, 256 threads (8 warps), warp tile 64x32 (warp grid 2x4).
// Operands split into tf32 hi+lo packed as float2; 3 mma passes (hh, hl, lh).

#define APAD 132
#define BPAD 132

__device__ __forceinline__ float2 split_tf32(float x) {
    uint32_t hu, lu;
    asm("cvt.rna.tf32.f32 %0, %1;" : "=r"(hu) : "f"(x));
    float hf = __uint_as_float(hu);
    asm("cvt.rna.tf32.f32 %0, %1;" : "=r"(lu) : "f"(x - hf));
    return make_float2(hf, __uint_as_float(lu));
}

__device__ __forceinline__ void mma_tf32(float& c0, float& c1, float& c2, float& c3,
                                         uint32_t a0, uint32_t a1, uint32_t a2, uint32_t a3,
                                         uint32_t b0, uint32_t b1) {
    asm volatile(
        "mma.sync.aligned.m16n8k8.row.col.f32.tf32.tf32.f32 "
        "{%0,%1,%2,%3}, {%4,%5,%6,%7}, {%8,%9}, {%0,%1,%2,%3};"
        : "+f"(c0), "+f"(c1), "+f"(c2), "+f"(c3)
        : "r"(a0), "r"(a1), "r"(a2), "r"(a3), "r"(b0), "r"(b1));
}

__global__ __launch_bounds__(256) void tf32_gemm_kernel(
    const float* __restrict__ A, const float* __restrict__ B,
    const float* __restrict__ bias, float* __restrict__ C,
    int M, int N, int K, int relu)
{
    __shared__ float2 As2[16 * APAD];   // [k][m], hi/lo pairs
    __shared__ float2 Bs2[16 * BPAD];   // [k][n], hi/lo pairs

    int tid = threadIdx.x;
    int wid = tid >> 5, lane = tid & 31;
    int g = lane >> 2, t4 = lane & 3;
    int warp_m = (wid >> 2) * 64;       // 0 or 64
    int warp_n = (wid & 3) * 32;        // 0,32,64,96
    int br = blockIdx.y * 128, bc = blockIdx.x * 128;

    // A tile load: thread -> (row, 8-k-chunk)
    int a_row = tid & 127;
    int a_k   = (tid >> 7) * 8;
    bool a_ok = (br + a_row) < M;
    const float* a_src = A + (size_t)(a_ok ? (br + a_row) : 0) * K + a_k;

    // B tile load (scalar-coalesced so smem stores are conflict-free):
    // thread -> (k-row = tid>>4, n = tid&15 + 16*i)
    int b_k = tid >> 4;
    int b_n = tid & 15;
    const float* b_src = B + (size_t)b_k * N + bc + b_n;

    float c[4][4][4];
#pragma unroll
    for (int i = 0; i < 4; i++)
#pragma unroll
        for (int j = 0; j < 4; j++)
#pragma unroll
            for (int r = 0; r < 4; r++) c[i][j][r] = 0.0f;

    // stage tile 0 in registers
    float ar[8], brg[8];
    {
        float4 v0 = a_ok ? *(const float4*)a_src : make_float4(0,0,0,0);
        float4 v1 = a_ok ? *(const float4*)(a_src + 4) : make_float4(0,0,0,0);
        ar[0]=v0.x; ar[1]=v0.y; ar[2]=v0.z; ar[3]=v0.w;
        ar[4]=v1.x; ar[5]=v1.y; ar[6]=v1.z; ar[7]=v1.w;
#pragma unroll
        for (int i = 0; i < 8; i++) brg[i] = b_src[16 * i];
    }

    for (int k0 = 0; k0 < K; k0 += 16) {
        // staged regs -> smem (with hi/lo split)
#pragma unroll
        for (int i = 0; i < 8; i++)
            As2[(a_k + i) * APAD + a_row] = split_tf32(ar[i]);
#pragma unroll
        for (int i = 0; i < 8; i++)
            Bs2[b_k * BPAD + b_n + 16 * i] = split_tf32(brg[i]);
        __syncthreads();

        // prefetch next tile
        if (k0 + 16 < K) {
            a_src += 16;
            b_src += (size_t)16 * N;
            float4 v0 = a_ok ? *(const float4*)a_src : make_float4(0,0,0,0);
            float4 v1 = a_ok ? *(const float4*)(a_src + 4) : make_float4(0,0,0,0);
            ar[0]=v0.x; ar[1]=v0.y; ar[2]=v0.z; ar[3]=v0.w;
            ar[4]=v1.x; ar[5]=v1.y; ar[6]=v1.z; ar[7]=v1.w;
#pragma unroll
            for (int i = 0; i < 8; i++) brg[i] = b_src[16 * i];
        }

        // compute: 2 k-slices of 8
#pragma unroll
        for (int ks = 0; ks < 16; ks += 8) {
            uint32_t ah[4][4], al[4][4];
#pragma unroll
            for (int mt = 0; mt < 4; mt++) {
                int m0 = warp_m + mt * 16 + g;
                float2 v0 = As2[(ks + t4) * APAD + m0];
                float2 v1 = As2[(ks + t4) * APAD + m0 + 8];
                float2 v2 = As2[(ks + t4 + 4) * APAD + m0];
                float2 v3 = As2[(ks + t4 + 4) * APAD + m0 + 8];
                ah[mt][0] = __float_as_uint(v0.x); al[mt][0] = __float_as_uint(v0.y);
                ah[mt][1] = __float_as_uint(v1.x); al[mt][1] = __float_as_uint(v1.y);
                ah[mt][2] = __float_as_uint(v2.x); al[mt][2] = __float_as_uint(v2.y);
                ah[mt][3] = __float_as_uint(v3.x); al[mt][3] = __float_as_uint(v3.y);
            }
#pragma unroll
            for (int nt = 0; nt < 4; nt++) {
                int n0 = warp_n + nt * 8 + g;
                float2 w0 = Bs2[(ks + t4) * BPAD + n0];
                float2 w1 = Bs2[(ks + t4 + 4) * BPAD + n0];
                uint32_t bh0 = __float_as_uint(w0.x), bl0 = __float_as_uint(w0.y);
                uint32_t bh1 = __float_as_uint(w1.x), bl1 = __float_as_uint(w1.y);
#pragma unroll
                for (int mt = 0; mt < 4; mt++) {
                    float* cc = c[mt][nt];
                    mma_tf32(cc[0], cc[1], cc[2], cc[3],
                             ah[mt][0], ah[mt][1], ah[mt][2], ah[mt][3], bh0, bh1);
                    mma_tf32(cc[0], cc[1], cc[2], cc[3],
                             ah[mt][0], ah[mt][1], ah[mt][2], ah[mt][3], bl0, bl1);
                    mma_tf32(cc[0], cc[1], cc[2], cc[3],
                             al[mt][0], al[mt][1], al[mt][2], al[mt][3], bh0, bh1);
                }
            }
        }
        __syncthreads();
    }

    // epilogue: bias + optional relu, float2 stores
#pragma unroll
    for (int mt = 0; mt < 4; mt++) {
#pragma unroll
        for (int nt = 0; nt < 4; nt++) {
            int r0 = br + warp_m + mt * 16 + g;
            int cc = bc + warp_n + nt * 8 + 2 * t4;
            float2 bv = *(const float2*)&bias[cc];
            float* a = c[mt][nt];
            if (r0 < M) {
                float2 v = make_float2(a[0] + bv.x, a[1] + bv.y);
                if (relu) { v.x = fmaxf(v.x, 0.f); v.y = fmaxf(v.y, 0.f); }
                *(float2*)&C[(size_t)r0 * N + cc] = v;
            }
            int r1 = r0 + 8;
            if (r1 < M) {
                float2 v = make_float2(a[2] + bv.x, a[3] + bv.y);
                if (relu) { v.x = fmaxf(v.x, 0.f); v.y = fmaxf(v.y, 0.f); }
                *(float2*)&C[(size_t)r1 * N + cc] = v;
            }
        }
    }
}

// ---------------- classifier: out[M,40] = A[M,128] @ W[128,40] + b ----------------
__global__ __launch_bounds__(256) void fc40_kernel(
    const float* __restrict__ A, const float* __restrict__ W,
    const float* __restrict__ bias, float* __restrict__ out, int M)
{
    __shared__ float Ws[DH * NCLS];
    for (int i = threadIdx.x; i < DH * NCLS; i += blockDim.x) Ws[i] = W[i];
    __syncthreads();

    int row = blockIdx.x * blockDim.x + threadIdx.x;
    if (row >= M) return;

    float acc[NCLS];
#pragma unroll
    for (int j = 0; j < NCLS; j++) acc[j] = bias[j];

    const float4* __restrict__ a4 = (const float4*)(A + (size_t)row * DH);
#pragma unroll 8
    for (int kc = 0; kc < DH / 4; kc++) {
        float4 av = a4[kc];
        int k = kc * 4;
        const float* w0 = &Ws[(k + 0) * NCLS];
        const float* w1 = &Ws[(k + 1) * NCLS];
        const float* w2 = &Ws[(k + 2) * NCLS];
        const float* w3 = &Ws[(k + 3) * NCLS];
#pragma unroll
        for (int j = 0; j < NCLS; j++)
            acc[j] += av.x * w0[j] + av.y * w1[j] + av.z * w2[j] + av.w * w3[j];
    }
    float* o = out + (size_t)row * NCLS;
#pragma unroll
    for (int j = 0; j < NCLS; j++) o[j] = acc[j];
}

// ---------------- launch ----------------
extern "C" void kernel_launch(void* const* d_in, const int* in_sizes, int n_in,
                              void* d_out, int out_size)
{
    const float* x    = (const float*)d_in[0];
    const void*  ei   = d_in[1];
    const float* W11  = (const float*)d_in[2];
    const float* b11  = (const float*)d_in[3];
    const float* W12  = (const float*)d_in[4];
    const float* b12  = (const float*)d_in[5];
    const float* W21  = (const float*)d_in[6];
    const float* b21  = (const float*)d_in[7];
    const float* W22  = (const float*)d_in[8];
    const float* b22  = (const float*)d_in[9];
    const float* Wfc  = (const float*)d_in[10];
    const float* bfc  = (const float*)d_in[11];

    int M = in_sizes[0] / DH;      // 50000
    int E = in_sizes[1] / 2;       // 800000

    float *p_agg, *p_h, *p_hidden;
    cudaGetSymbolAddress((void**)&p_agg, g_agg);
    cudaGetSymbolAddress((void**)&p_h, g_h);
    cudaGetSymbolAddress((void**)&p_hidden, g_hidden);
    int* p_cnt;
    cudaGetSymbolAddress((void**)&p_cnt, g_cnt);

    detect_dtype_kernel<<<1, 32>>>((const int*)ei, 2 * E);

    // CSR build: count -> parallel atomic reservation -> fill (no serial scan)
    zero_int_kernel<<<(M + 255) / 256, 256>>>(p_cnt, M);
    count_kernel<<<(E + 255) / 256, 256>>>(ei, E);
    reserve_kernel<<<(M + 255) / 256, 256>>>(M);
    fill_kernel<<<(E + 255) / 256, 256>>>(ei, E);

    int agg_blocks = (M + 7) / 8;
    dim3 g1(2, (M + 127) / 128);   // N=256
    dim3 g2(1, (M + 127) / 128);   // N=128

    // Layer 1
    agg_kernel<<<agg_blocks, 256>>>(x, p_agg, M);
    tf32_gemm_kernel<<<g1, 256>>>(p_agg, W11, b11, p_hidden, M, 2 * DH, DH, 1);
    tf32_gemm_kernel<<<g2, 256>>>(p_hidden, W12, b12, p_h, M, DH, 2 * DH, 1);

    // Layer 2
    agg_kernel<<<agg_blocks, 256>>>(p_h, p_agg, M);
    tf32_gemm_kernel<<<g1, 256>>>(p_agg, W21, b21, p_hidden, M, 2 * DH, DH, 1);
    tf32_gemm_kernel<<<g2, 256>>>(p_hidden, W22, b22, p_h, M, DH, 2 * DH, 1);

    // Classifier
    fc40_kernel<<<(M + 255) / 256, 256>>>(p_h, Wfc, bfc, (float*)d_out, M);
}

// round 8
// speedup vs baseline: 1.7001x; 1.4532x over previous
#include <cuda_runtime.h>
#include <cuda_bf16.h>
#include <cstdint>

#define NN 50000
#define EE 800000
#define DH 128
#define NCLS 40

// ---------------- scratch ----------------
__device__ __align__(16) float g_agg[NN * DH];
__device__ __align__(16) float g_h[NN * DH];
__device__ __align__(16) float g_hidden[NN * 2 * DH];
__device__ int g_cnt[NN];
__device__ int g_rowptr[NN];
__device__ int g_cursor[NN];
__device__ int g_col[EE];
__device__ int g_total;
__device__ int g_is64;
// split/transposed weights: [N,K] bf16, hi & lo. 4 slots of 32768 elements.
__device__ __align__(16) __nv_bfloat16 g_whi[4 * 32768];
__device__ __align__(16) __nv_bfloat16 g_wlo[4 * 32768];

// ---------------- dtype detection ----------------
__global__ void detect_dtype_kernel(const int* __restrict__ ei32, int n_words) {
    if (threadIdx.x == 0 && blockIdx.x == 0) {
        int all_zero = 1;
        for (int k = 0; k < 128; k++) {
            int idx = 2 * k + 1;
            if (idx < n_words && ei32[idx] != 0) { all_zero = 0; break; }
        }
        g_is64 = all_zero;
    }
}

// ---------------- CSR build (scan-free) ----------------
__global__ void zero_int_kernel(int* p, int n) {
    int i = blockIdx.x * blockDim.x + threadIdx.x;
    if (i < n) p[i] = 0;
    if (i == 0) g_total = 0;
}

__global__ void count_kernel(const void* __restrict__ ei, int E) {
    int e = blockIdx.x * blockDim.x + threadIdx.x;
    if (e >= E) return;
    int d;
    if (g_is64) d = (int)((const long long*)ei)[E + e];
    else        d = ((const int*)ei)[E + e];
    atomicAdd(&g_cnt[d], 1);
}

__global__ void reserve_kernel(int n) {
    int i = blockIdx.x * blockDim.x + threadIdx.x;
    if (i >= n) return;
    int c = g_cnt[i];
    int s = atomicAdd(&g_total, c);
    g_rowptr[i] = s;
    g_cursor[i] = s;
}

__global__ void fill_kernel(const void* __restrict__ ei, int E) {
    int e = blockIdx.x * blockDim.x + threadIdx.x;
    if (e >= E) return;
    int s, d;
    if (g_is64) {
        s = (int)((const long long*)ei)[e];
        d = (int)((const long long*)ei)[E + e];
    } else {
        s = ((const int*)ei)[e];
        d = ((const int*)ei)[E + e];
    }
    int pos = atomicAdd(&g_cursor[d], 1);
    g_col[pos] = s;
}

// ---------------- aggregation ----------------
__global__ void agg_kernel(const float* __restrict__ x, float* __restrict__ out, int M) {
    int node = blockIdx.x * (blockDim.x >> 5) + (threadIdx.x >> 5);
    if (node >= M) return;
    int lane = threadIdx.x & 31;
    const float4* x4 = (const float4*)x;
    float4* out4 = (float4*)out;
    size_t base = (size_t)node * 32 + lane;
    float4 acc = x4[base];
    int e = g_rowptr[node];
    int end = g_cursor[node];
    for (; e + 4 <= end; e += 4) {
        int s0 = g_col[e], s1 = g_col[e + 1], s2 = g_col[e + 2], s3 = g_col[e + 3];
        float4 v0 = __ldg(&x4[(size_t)s0 * 32 + lane]);
        float4 v1 = __ldg(&x4[(size_t)s1 * 32 + lane]);
        float4 v2 = __ldg(&x4[(size_t)s2 * 32 + lane]);
        float4 v3 = __ldg(&x4[(size_t)s3 * 32 + lane]);
        acc.x += (v0.x + v1.x) + (v2.x + v3.x);
        acc.y += (v0.y + v1.y) + (v2.y + v3.y);
        acc.z += (v0.z + v1.z) + (v2.z + v3.z);
        acc.w += (v0.w + v1.w) + (v2.w + v3.w);
    }
    for (; e < end; e++) {
        int s = g_col[e];
        float4 v = __ldg(&x4[(size_t)s * 32 + lane]);
        acc.x += v.x; acc.y += v.y; acc.z += v.z; acc.w += v.w;
    }
    out4[base] = acc;
}

// ---------------- weight transpose + bf16 hi/lo split ----------------
// W: [K,N] f32 row-major  ->  hi/lo: [N,K] bf16 (K contiguous)
__global__ void split_w_kernel(const float* __restrict__ W,
                               __nv_bfloat16* __restrict__ hi,
                               __nv_bfloat16* __restrict__ lo,
                               int K, int N) {
    int i = blockIdx.x * blockDim.x + threadIdx.x;
    if (i >= N * K) return;
    int n = i / K, k = i - n * K;
    float x = W[(size_t)k * N + n];
    __nv_bfloat16 h = __float2bfloat16(x);
    hi[i] = h;
    lo[i] = __float2bfloat16(x - __bfloat162float(h));
}

// ---------------- split-bf16 mma.sync GEMM ----------------
// C[M,N] = relu?(A[M,K] @ W + bias), W pre-split as Whi/Wlo [N,K] bf16.
// Block 128x128x32, 256 threads, warp tile 64x32 (warp grid 2x4).
// mma.sync.m16n8k16, 3 passes (hh, hl, lh).
// smem: [row][SA uints], SA=20 -> fragment loads conflict-free (20g mod 32 disjoint).

#define SA 20

__device__ __forceinline__ void mma_bf16(float& c0, float& c1, float& c2, float& c3,
                                         uint32_t a0, uint32_t a1, uint32_t a2, uint32_t a3,
                                         uint32_t b0, uint32_t b1) {
    asm volatile(
        "mma.sync.aligned.m16n8k16.row.col.f32.bf16.bf16.f32 "
        "{%0,%1,%2,%3}, {%4,%5,%6,%7}, {%8,%9}, {%0,%1,%2,%3};"
        : "+f"(c0), "+f"(c1), "+f"(c2), "+f"(c3)
        : "r"(a0), "r"(a1), "r"(a2), "r"(a3), "r"(b0), "r"(b1));
}

__global__ __launch_bounds__(256) void bf16_gemm_kernel(
    const float* __restrict__ A,
    const __nv_bfloat16* __restrict__ Whi,
    const __nv_bfloat16* __restrict__ Wlo,
    const float* __restrict__ bias,
    float* __restrict__ C,
    int M, int N, int K, int relu)
{
    __shared__ uint32_t Ah[128 * SA];
    __shared__ uint32_t Al[128 * SA];
    __shared__ uint32_t Bh[128 * SA];
    __shared__ uint32_t Bl[128 * SA];

    int tid = threadIdx.x;
    int wid = tid >> 5, lane = tid & 31;
    int g = lane >> 2, t4 = lane & 3;
    int warp_m = (wid >> 2) * 64;       // 0 or 64
    int warp_n = (wid & 3) * 32;        // 0,32,64,96
    int br = blockIdx.y * 128, bc = blockIdx.x * 128;

    // tile load mapping: 2 threads per row, each covers 16 k-values (8 pairs)
    int row = tid >> 1;
    int ks2 = (tid & 1) * 8;            // pair offset within 16-pair row
    bool a_ok = (br + row) < M;
    const float* a_src = A + (size_t)(a_ok ? (br + row) : 0) * K + ks2 * 2;
    const __nv_bfloat16* bh_src = Whi + (size_t)(bc + row) * K + ks2 * 2;
    const __nv_bfloat16* bl_src = Wlo + (size_t)(bc + row) * K + ks2 * 2;

    float acc[4][4][4];
#pragma unroll
    for (int i = 0; i < 4; i++)
#pragma unroll
        for (int j = 0; j < 4; j++)
#pragma unroll
            for (int r = 0; r < 4; r++) acc[i][j][r] = 0.0f;

    // prefetch tile 0
    float4 f[4];
    uint4 pbh[2], pbl[2];
    {
        if (a_ok) {
            const float4* ap = (const float4*)a_src;
            f[0] = ap[0]; f[1] = ap[1]; f[2] = ap[2]; f[3] = ap[3];
        } else {
            f[0] = f[1] = f[2] = f[3] = make_float4(0.f, 0.f, 0.f, 0.f);
        }
        const uint4* hp = (const uint4*)bh_src;
        const uint4* lp = (const uint4*)bl_src;
        pbh[0] = hp[0]; pbh[1] = hp[1];
        pbl[0] = lp[0]; pbl[1] = lp[1];
    }

    for (int k0 = 0; k0 < K; k0 += 32) {
        // ---- staged regs -> smem ----
        uint32_t rb = row * SA + ks2;
#pragma unroll
        for (int j = 0; j < 4; j++) {
            float xs[4] = {f[j].x, f[j].y, f[j].z, f[j].w};
#pragma unroll
            for (int p = 0; p < 2; p++) {
                float x0 = xs[2 * p], x1 = xs[2 * p + 1];
                __nv_bfloat162 h = __float22bfloat162_rn(make_float2(x0, x1));
                float l0 = x0 - __bfloat162float(h.x);
                float l1 = x1 - __bfloat162float(h.y);
                __nv_bfloat162 l = __float22bfloat162_rn(make_float2(l0, l1));
                Ah[rb + 2 * j + p] = *(uint32_t*)&h;
                Al[rb + 2 * j + p] = *(uint32_t*)&l;
            }
        }
        *(uint4*)&Bh[rb] = pbh[0];
        *(uint4*)&Bh[rb + 4] = pbh[1];
        *(uint4*)&Bl[rb] = pbl[0];
        *(uint4*)&Bl[rb + 4] = pbl[1];
        __syncthreads();

        // ---- prefetch next tile ----
        if (k0 + 32 < K) {
            a_src += 32; bh_src += 32; bl_src += 32;
            if (a_ok) {
                const float4* ap = (const float4*)a_src;
                f[0] = ap[0]; f[1] = ap[1]; f[2] = ap[2]; f[3] = ap[3];
            }
            const uint4* hp = (const uint4*)bh_src;
            const uint4* lp = (const uint4*)bl_src;
            pbh[0] = hp[0]; pbh[1] = hp[1];
            pbl[0] = lp[0]; pbl[1] = lp[1];
        }

        // ---- compute: 2 k16-slices ----
#pragma unroll
        for (int s = 0; s < 2; s++) {
            int so = s * 8;
            uint32_t ah[4][4], al[4][4];
#pragma unroll
            for (int mt = 0; mt < 4; mt++) {
                int m0 = warp_m + mt * 16 + g;
                uint32_t i0 = m0 * SA + so + t4;
                uint32_t i1 = (m0 + 8) * SA + so + t4;
                ah[mt][0] = Ah[i0];     ah[mt][1] = Ah[i1];
                ah[mt][2] = Ah[i0 + 4]; ah[mt][3] = Ah[i1 + 4];
                al[mt][0] = Al[i0];     al[mt][1] = Al[i1];
                al[mt][2] = Al[i0 + 4]; al[mt][3] = Al[i1 + 4];
            }
#pragma unroll
            for (int nt = 0; nt < 4; nt++) {
                int n0 = warp_n + nt * 8 + g;
                uint32_t ib = n0 * SA + so + t4;
                uint32_t bh0 = Bh[ib], bh1 = Bh[ib + 4];
                uint32_t bl0 = Bl[ib], bl1 = Bl[ib + 4];
#pragma unroll
                for (int mt = 0; mt < 4; mt++) {
                    float* cc = acc[mt][nt];
                    mma_bf16(cc[0], cc[1], cc[2], cc[3],
                             ah[mt][0], ah[mt][1], ah[mt][2], ah[mt][3], bh0, bh1);
                    mma_bf16(cc[0], cc[1], cc[2], cc[3],
                             ah[mt][0], ah[mt][1], ah[mt][2], ah[mt][3], bl0, bl1);
                    mma_bf16(cc[0], cc[1], cc[2], cc[3],
                             al[mt][0], al[mt][1], al[mt][2], al[mt][3], bh0, bh1);
                }
            }
        }
        __syncthreads();
    }

    // ---- epilogue: bias + optional relu ----
#pragma unroll
    for (int mt = 0; mt < 4; mt++) {
#pragma unroll
        for (int nt = 0; nt < 4; nt++) {
            int r0 = br + warp_m + mt * 16 + g;
            int cc = bc + warp_n + nt * 8 + 2 * t4;
            float2 bv = *(const float2*)&bias[cc];
            float* a = acc[mt][nt];
            if (r0 < M) {
                float2 v = make_float2(a[0] + bv.x, a[1] + bv.y);
                if (relu) { v.x = fmaxf(v.x, 0.f); v.y = fmaxf(v.y, 0.f); }
                *(float2*)&C[(size_t)r0 * N + cc] = v;
            }
            int r1 = r0 + 8;
            if (r1 < M) {
                float2 v = make_float2(a[2] + bv.x, a[3] + bv.y);
                if (relu) { v.x = fmaxf(v.x, 0.f); v.y = fmaxf(v.y, 0.f); }
                *(float2*)&C[(size_t)r1 * N + cc] = v;
            }
        }
    }
}

// ---------------- classifier: out[M,40] = A[M,128] @ W[128,40] + b ----------------
__global__ __launch_bounds__(256) void fc40_kernel(
    const float* __restrict__ A, const float* __restrict__ W,
    const float* __restrict__ bias, float* __restrict__ out, int M)
{
    __shared__ float Ws[DH * NCLS];
    for (int i = threadIdx.x; i < DH * NCLS; i += blockDim.x) Ws[i] = W[i];
    __syncthreads();

    int row = blockIdx.x * blockDim.x + threadIdx.x;
    if (row >= M) return;

    float acc[NCLS];
#pragma unroll
    for (int j = 0; j < NCLS; j++) acc[j] = bias[j];

    const float4* __restrict__ a4 = (const float4*)(A + (size_t)row * DH);
#pragma unroll 8
    for (int kc = 0; kc < DH / 4; kc++) {
        float4 av = a4[kc];
        int k = kc * 4;
        const float* w0 = &Ws[(k + 0) * NCLS];
        const float* w1 = &Ws[(k + 1) * NCLS];
        const float* w2 = &Ws[(k + 2) * NCLS];
        const float* w3 = &Ws[(k + 3) * NCLS];
#pragma unroll
        for (int j = 0; j < NCLS; j++)
            acc[j] += av.x * w0[j] + av.y * w1[j] + av.z * w2[j] + av.w * w3[j];
    }
    float* o = out + (size_t)row * NCLS;
#pragma unroll
    for (int j = 0; j < NCLS; j++) o[j] = acc[j];
}

// ---------------- launch ----------------
extern "C" void kernel_launch(void* const* d_in, const int* in_sizes, int n_in,
                              void* d_out, int out_size)
{
    const float* x    = (const float*)d_in[0];
    const void*  ei   = d_in[1];
    const float* W11  = (const float*)d_in[2];
    const float* b11  = (const float*)d_in[3];
    const float* W12  = (const float*)d_in[4];
    const float* b12  = (const float*)d_in[5];
    const float* W21  = (const float*)d_in[6];
    const float* b21  = (const float*)d_in[7];
    const float* W22  = (const float*)d_in[8];
    const float* b22  = (const float*)d_in[9];
    const float* Wfc  = (const float*)d_in[10];
    const float* bfc  = (const float*)d_in[11];

    int M = in_sizes[0] / DH;      // 50000
    int E = in_sizes[1] / 2;       // 800000

    float *p_agg, *p_h, *p_hidden;
    cudaGetSymbolAddress((void**)&p_agg, g_agg);
    cudaGetSymbolAddress((void**)&p_h, g_h);
    cudaGetSymbolAddress((void**)&p_hidden, g_hidden);
    int* p_cnt;
    cudaGetSymbolAddress((void**)&p_cnt, g_cnt);
    __nv_bfloat16 *p_whi, *p_wlo;
    cudaGetSymbolAddress((void**)&p_whi, g_whi);
    cudaGetSymbolAddress((void**)&p_wlo, g_wlo);

    detect_dtype_kernel<<<1, 32>>>((const int*)ei, 2 * E);

    // CSR build
    zero_int_kernel<<<(M + 255) / 256, 256>>>(p_cnt, M);
    count_kernel<<<(E + 255) / 256, 256>>>(ei, E);
    reserve_kernel<<<(M + 255) / 256, 256>>>(M);
    fill_kernel<<<(E + 255) / 256, 256>>>(ei, E);

    // weight transpose + split (each 32768 elements)
    const int WS = 32768;
    split_w_kernel<<<WS / 256, 256>>>(W11, p_whi + 0 * WS, p_wlo + 0 * WS, 128, 256);
    split_w_kernel<<<WS / 256, 256>>>(W12, p_whi + 1 * WS, p_wlo + 1 * WS, 256, 128);
    split_w_kernel<<<WS / 256, 256>>>(W21, p_whi + 2 * WS, p_wlo + 2 * WS, 128, 256);
    split_w_kernel<<<WS / 256, 256>>>(W22, p_whi + 3 * WS, p_wlo + 3 * WS, 256, 128);

    int agg_blocks = (M + 7) / 8;
    dim3 g1(2, (M + 127) / 128);   // N=256
    dim3 g2(1, (M + 127) / 128);   // N=128

    // Layer 1
    agg_kernel<<<agg_blocks, 256>>>(x, p_agg, M);
    bf16_gemm_kernel<<<g1, 256>>>(p_agg, p_whi + 0 * WS, p_wlo + 0 * WS, b11, p_hidden, M, 256, 128, 1);
    bf16_gemm_kernel<<<g2, 256>>>(p_hidden, p_whi + 1 * WS, p_wlo + 1 * WS, b12, p_h, M, 128, 256, 1);

    // Layer 2
    agg_kernel<<<agg_blocks, 256>>>(p_h, p_agg, M);
    bf16_gemm_kernel<<<g1, 256>>>(p_agg, p_whi + 2 * WS, p_wlo + 2 * WS, b21, p_hidden, M, 256, 128, 1);
    bf16_gemm_kernel<<<g2, 256>>>(p_hidden, p_whi + 3 * WS, p_wlo + 3 * WS, b22, p_h, M, 128, 256, 1);

    // Classifier
    fc40_kernel<<<(M + 255) / 256, 256>>>(p_h, Wfc, bfc, (float*)d_out, M);
}

// round 9
// speedup vs baseline: 1.9190x; 1.1287x over previous
#include <cuda_runtime.h>
#include <cuda_bf16.h>
#include <cuda_fp16.h>
#include <cstdint>

#define NN 50000
#define EE 800000
#define DH 128
#define NCLS 40

// ---------------- scratch ----------------
__device__ __align__(16) float g_agg[NN * DH];
__device__ __align__(16) float g_h[NN * DH];
__device__ __align__(16) float g_hidden[NN * 2 * DH];
__device__ int g_cnt[NN];
__device__ int g_rowptr[NN];
__device__ int g_cursor[NN];
__device__ int g_col[EE];
__device__ int g_total;
__device__ int g_is64;
// transposed fp16 weights: [N,K]. 4 slots of 32768 elements.
__device__ __align__(16) __half g_wh[4 * 32768];

// ---------------- dtype detection ----------------
__global__ void detect_dtype_kernel(const int* __restrict__ ei32, int n_words) {
    if (threadIdx.x == 0 && blockIdx.x == 0) {
        int all_zero = 1;
        for (int k = 0; k < 128; k++) {
            int idx = 2 * k + 1;
            if (idx < n_words && ei32[idx] != 0) { all_zero = 0; break; }
        }
        g_is64 = all_zero;
    }
}

// ---------------- CSR build (scan-free) ----------------
__global__ void zero_int_kernel(int* p, int n) {
    int i = blockIdx.x * blockDim.x + threadIdx.x;
    if (i < n) p[i] = 0;
    if (i == 0) g_total = 0;
}

__global__ void count_kernel(const void* __restrict__ ei, int E) {
    int e = blockIdx.x * blockDim.x + threadIdx.x;
    if (e >= E) return;
    int d;
    if (g_is64) d = (int)((const long long*)ei)[E + e];
    else        d = ((const int*)ei)[E + e];
    atomicAdd(&g_cnt[d], 1);
}

__global__ void reserve_kernel(int n) {
    int i = blockIdx.x * blockDim.x + threadIdx.x;
    if (i >= n) return;
    int c = g_cnt[i];
    int s = atomicAdd(&g_total, c);
    g_rowptr[i] = s;
    g_cursor[i] = s;
}

__global__ void fill_kernel(const void* __restrict__ ei, int E) {
    int e = blockIdx.x * blockDim.x + threadIdx.x;
    if (e >= E) return;
    int s, d;
    if (g_is64) {
        s = (int)((const long long*)ei)[e];
        d = (int)((const long long*)ei)[E + e];
    } else {
        s = ((const int*)ei)[e];
        d = ((const int*)ei)[E + e];
    }
    int pos = atomicAdd(&g_cursor[d], 1);
    g_col[pos] = s;
}

// ---------------- aggregation ----------------
__global__ void agg_kernel(const float* __restrict__ x, float* __restrict__ out, int M) {
    int node = blockIdx.x * (blockDim.x >> 5) + (threadIdx.x >> 5);
    if (node >= M) return;
    int lane = threadIdx.x & 31;
    const float4* x4 = (const float4*)x;
    float4* out4 = (float4*)out;
    size_t base = (size_t)node * 32 + lane;
    float4 acc = x4[base];
    int e = g_rowptr[node];
    int end = g_cursor[node];
    for (; e + 4 <= end; e += 4) {
        int s0 = g_col[e], s1 = g_col[e + 1], s2 = g_col[e + 2], s3 = g_col[e + 3];
        float4 v0 = __ldg(&x4[(size_t)s0 * 32 + lane]);
        float4 v1 = __ldg(&x4[(size_t)s1 * 32 + lane]);
        float4 v2 = __ldg(&x4[(size_t)s2 * 32 + lane]);
        float4 v3 = __ldg(&x4[(size_t)s3 * 32 + lane]);
        acc.x += (v0.x + v1.x) + (v2.x + v3.x);
        acc.y += (v0.y + v1.y) + (v2.y + v3.y);
        acc.z += (v0.z + v1.z) + (v2.z + v3.z);
        acc.w += (v0.w + v1.w) + (v2.w + v3.w);
    }
    for (; e < end; e++) {
        int s = g_col[e];
        float4 v = __ldg(&x4[(size_t)s * 32 + lane]);
        acc.x += v.x; acc.y += v.y; acc.z += v.z; acc.w += v.w;
    }
    out4[base] = acc;
}

// ---------------- weight transpose + fp16 convert ----------------
// W: [K,N] f32 row-major  ->  out: [N,K] fp16 (K contiguous)
__global__ void conv_w_kernel(const float* __restrict__ W,
                              __half* __restrict__ out, int K, int N) {
    int i = blockIdx.x * blockDim.x + threadIdx.x;
    if (i >= N * K) return;
    int n = i / K, k = i - n * K;
    out[i] = __float2half(W[(size_t)k * N + n]);
}

// ---------------- fp16 2-pass mma.sync GEMM ----------------
// C[M,N] = relu?(A[M,K] @ W + bias), W pre-converted fp16 [N,K].
// A split into fp16 hi+lo (A ~ Ah+Al to ~22 bits); C = Ah*B + Al*B.
// Block 128x128x32, 256 threads, warp tile 64x32 (warp grid 2x4).
// smem: [row][SA uints], SA=20 -> fragment loads conflict-free.

#define SA 20

__device__ __forceinline__ void mma_fp16(float& c0, float& c1, float& c2, float& c3,
                                         uint32_t a0, uint32_t a1, uint32_t a2, uint32_t a3,
                                         uint32_t b0, uint32_t b1) {
    asm volatile(
        "mma.sync.aligned.m16n8k16.row.col.f32.f16.f16.f32 "
        "{%0,%1,%2,%3}, {%4,%5,%6,%7}, {%8,%9}, {%0,%1,%2,%3};"
        : "+f"(c0), "+f"(c1), "+f"(c2), "+f"(c3)
        : "r"(a0), "r"(a1), "r"(a2), "r"(a3), "r"(b0), "r"(b1));
}

__global__ __launch_bounds__(256, 2) void fp16_gemm_kernel(
    const float* __restrict__ A,
    const __half* __restrict__ Wh,
    const float* __restrict__ bias,
    float* __restrict__ C,
    int M, int N, int K, int relu)
{
    __shared__ uint32_t Ah[128 * SA];
    __shared__ uint32_t Al[128 * SA];
    __shared__ uint32_t Bh[128 * SA];

    int tid = threadIdx.x;
    int wid = tid >> 5, lane = tid & 31;
    int g = lane >> 2, t4 = lane & 3;
    int warp_m = (wid >> 2) * 64;       // 0 or 64
    int warp_n = (wid & 3) * 32;        // 0,32,64,96
    int br = blockIdx.y * 128, bc = blockIdx.x * 128;

    // tile load mapping: 2 threads per row, each covers 16 k-values
    int row = tid >> 1;
    int ks2 = (tid & 1) * 8;            // uint offset within 16-uint row
    bool a_ok = (br + row) < M;
    const float* a_src = A + (size_t)(a_ok ? (br + row) : 0) * K + ks2 * 2;
    const __half* b_src = Wh + (size_t)(bc + row) * K + ks2 * 2;

    float acc[4][4][4];
#pragma unroll
    for (int i = 0; i < 4; i++)
#pragma unroll
        for (int j = 0; j < 4; j++)
#pragma unroll
            for (int r = 0; r < 4; r++) acc[i][j][r] = 0.0f;

    // prefetch tile 0
    float4 f[4];
    uint4 pbh[2];
    {
        if (a_ok) {
            const float4* ap = (const float4*)a_src;
            f[0] = ap[0]; f[1] = ap[1]; f[2] = ap[2]; f[3] = ap[3];
        } else {
            f[0] = f[1] = f[2] = f[3] = make_float4(0.f, 0.f, 0.f, 0.f);
        }
        const uint4* hp = (const uint4*)b_src;
        pbh[0] = hp[0]; pbh[1] = hp[1];
    }

    for (int k0 = 0; k0 < K; k0 += 32) {
        // ---- staged regs -> smem (A split hi/lo) ----
        uint32_t rb = row * SA + ks2;
#pragma unroll
        for (int j = 0; j < 4; j++) {
            float xs[4] = {f[j].x, f[j].y, f[j].z, f[j].w};
#pragma unroll
            for (int p = 0; p < 2; p++) {
                float x0 = xs[2 * p], x1 = xs[2 * p + 1];
                __half2 h = __float22half2_rn(make_float2(x0, x1));
                float l0 = x0 - __half2float(__low2half(h));
                float l1 = x1 - __half2float(__high2half(h));
                __half2 l = __float22half2_rn(make_float2(l0, l1));
                Ah[rb + 2 * j + p] = *(uint32_t*)&h;
                Al[rb + 2 * j + p] = *(uint32_t*)&l;
            }
        }
        *(uint4*)&Bh[rb] = pbh[0];
        *(uint4*)&Bh[rb + 4] = pbh[1];
        __syncthreads();

        // ---- prefetch next tile ----
        if (k0 + 32 < K) {
            a_src += 32; b_src += 32;
            if (a_ok) {
                const float4* ap = (const float4*)a_src;
                f[0] = ap[0]; f[1] = ap[1]; f[2] = ap[2]; f[3] = ap[3];
            }
            const uint4* hp = (const uint4*)b_src;
            pbh[0] = hp[0]; pbh[1] = hp[1];
        }

        // ---- compute: 2 k16-slices ----
#pragma unroll
        for (int s = 0; s < 2; s++) {
            int so = s * 8;
            uint32_t ah[4][4], al[4][4];
#pragma unroll
            for (int mt = 0; mt < 4; mt++) {
                int m0 = warp_m + mt * 16 + g;
                uint32_t i0 = m0 * SA + so + t4;
                uint32_t i1 = (m0 + 8) * SA + so + t4;
                ah[mt][0] = Ah[i0];     ah[mt][1] = Ah[i1];
                ah[mt][2] = Ah[i0 + 4]; ah[mt][3] = Ah[i1 + 4];
                al[mt][0] = Al[i0];     al[mt][1] = Al[i1];
                al[mt][2] = Al[i0 + 4]; al[mt][3] = Al[i1 + 4];
            }
#pragma unroll
            for (int nt = 0; nt < 4; nt++) {
                int n0 = warp_n + nt * 8 + g;
                uint32_t ib = n0 * SA + so + t4;
                uint32_t bh0 = Bh[ib], bh1 = Bh[ib + 4];
#pragma unroll
                for (int mt = 0; mt < 4; mt++) {
                    float* cc = acc[mt][nt];
                    mma_fp16(cc[0], cc[1], cc[2], cc[3],
                             ah[mt][0], ah[mt][1], ah[mt][2], ah[mt][3], bh0, bh1);
                    mma_fp16(cc[0], cc[1], cc[2], cc[3],
                             al[mt][0], al[mt][1], al[mt][2], al[mt][3], bh0, bh1);
                }
            }
        }
        __syncthreads();
    }

    // ---- epilogue: bias + optional relu ----
#pragma unroll
    for (int mt = 0; mt < 4; mt++) {
#pragma unroll
        for (int nt = 0; nt < 4; nt++) {
            int r0 = br + warp_m + mt * 16 + g;
            int cc = bc + warp_n + nt * 8 + 2 * t4;
            float2 bv = *(const float2*)&bias[cc];
            float* a = acc[mt][nt];
            if (r0 < M) {
                float2 v = make_float2(a[0] + bv.x, a[1] + bv.y);
                if (relu) { v.x = fmaxf(v.x, 0.f); v.y = fmaxf(v.y, 0.f); }
                *(float2*)&C[(size_t)r0 * N + cc] = v;
            }
            int r1 = r0 + 8;
            if (r1 < M) {
                float2 v = make_float2(a[2] + bv.x, a[3] + bv.y);
                if (relu) { v.x = fmaxf(v.x, 0.f); v.y = fmaxf(v.y, 0.f); }
                *(float2*)&C[(size_t)r1 * N + cc] = v;
            }
        }
    }
}

// ---------------- classifier: out[M,40] = A[M,128] @ W[128,40] + b ----------------
__global__ __launch_bounds__(256) void fc40_kernel(
    const float* __restrict__ A, const float* __restrict__ W,
    const float* __restrict__ bias, float* __restrict__ out, int M)
{
    __shared__ float Ws[DH * NCLS];
    for (int i = threadIdx.x; i < DH * NCLS; i += blockDim.x) Ws[i] = W[i];
    __syncthreads();

    int row = blockIdx.x * blockDim.x + threadIdx.x;
    if (row >= M) return;

    float acc[NCLS];
#pragma unroll
    for (int j = 0; j < NCLS; j++) acc[j] = bias[j];

    const float4* __restrict__ a4 = (const float4*)(A + (size_t)row * DH);
#pragma unroll 8
    for (int kc = 0; kc < DH / 4; kc++) {
        float4 av = a4[kc];
        int k = kc * 4;
        const float* w0 = &Ws[(k + 0) * NCLS];
        const float* w1 = &Ws[(k + 1) * NCLS];
        const float* w2 = &Ws[(k + 2) * NCLS];
        const float* w3 = &Ws[(k + 3) * NCLS];
#pragma unroll
        for (int j = 0; j < NCLS; j++)
            acc[j] += av.x * w0[j] + av.y * w1[j] + av.z * w2[j] + av.w * w3[j];
    }
    float* o = out + (size_t)row * NCLS;
#pragma unroll
    for (int j = 0; j < NCLS; j++) o[j] = acc[j];
}

// ---------------- launch ----------------
extern "C" void kernel_launch(void* const* d_in, const int* in_sizes, int n_in,
                              void* d_out, int out_size)
{
    const float* x    = (const float*)d_in[0];
    const void*  ei   = d_in[1];
    const float* W11  = (const float*)d_in[2];
    const float* b11  = (const float*)d_in[3];
    const float* W12  = (const float*)d_in[4];
    const float* b12  = (const float*)d_in[5];
    const float* W21  = (const float*)d_in[6];
    const float* b21  = (const float*)d_in[7];
    const float* W22  = (const float*)d_in[8];
    const float* b22  = (const float*)d_in[9];
    const float* Wfc  = (const float*)d_in[10];
    const float* bfc  = (const float*)d_in[11];

    int M = in_sizes[0] / DH;      // 50000
    int E = in_sizes[1] / 2;       // 800000

    float *p_agg, *p_h, *p_hidden;
    cudaGetSymbolAddress((void**)&p_agg, g_agg);
    cudaGetSymbolAddress((void**)&p_h, g_h);
    cudaGetSymbolAddress((void**)&p_hidden, g_hidden);
    int* p_cnt;
    cudaGetSymbolAddress((void**)&p_cnt, g_cnt);
    __half* p_wh;
    cudaGetSymbolAddress((void**)&p_wh, g_wh);

    detect_dtype_kernel<<<1, 32>>>((const int*)ei, 2 * E);

    // CSR build
    zero_int_kernel<<<(M + 255) / 256, 256>>>(p_cnt, M);
    count_kernel<<<(E + 255) / 256, 256>>>(ei, E);
    reserve_kernel<<<(M + 255) / 256, 256>>>(M);
    fill_kernel<<<(E + 255) / 256, 256>>>(ei, E);

    // weight transpose + fp16 convert (each 32768 elements)
    const int WS = 32768;
    conv_w_kernel<<<WS / 256, 256>>>(W11, p_wh + 0 * WS, 128, 256);
    conv_w_kernel<<<WS / 256, 256>>>(W12, p_wh + 1 * WS, 256, 128);
    conv_w_kernel<<<WS / 256, 256>>>(W21, p_wh + 2 * WS, 128, 256);
    conv_w_kernel<<<WS / 256, 256>>>(W22, p_wh + 3 * WS, 256, 128);

    int agg_blocks = (M + 7) / 8;
    dim3 g1(2, (M + 127) / 128);   // N=256
    dim3 g2(1, (M + 127) / 128);   // N=128

    // Layer 1
    agg_kernel<<<agg_blocks, 256>>>(x, p_agg, M);
    fp16_gemm_kernel<<<g1, 256>>>(p_agg, p_wh + 0 * WS, b11, p_hidden, M, 256, 128, 1);
    fp16_gemm_kernel<<<g2, 256>>>(p_hidden, p_wh + 1 * WS, b12, p_h, M, 128, 256, 1);

    // Layer 2
    agg_kernel<<<agg_blocks, 256>>>(p_h, p_agg, M);
    fp16_gemm_kernel<<<g1, 256>>>(p_agg, p_wh + 2 * WS, b21, p_hidden, M, 256, 128, 1);
    fp16_gemm_kernel<<<g2, 256>>>(p_hidden, p_wh + 3 * WS, b22, p_h, M, 128, 256, 1);

    // Classifier
    fc40_kernel<<<(M + 255) / 256, 256>>>(p_h, Wfc, bfc, (float*)d_out, M);
}

// round 10
// speedup vs baseline: 1.9789x; 1.0312x over previous
#include <cuda_runtime.h>
#include <cuda_bf16.h>
#include <cuda_fp16.h>
#include <cstdint>

#define NN 50000
#define EE 800000
#define DH 128
#define NCLS 40

// ---------------- scratch ----------------
__device__ __align__(16) float g_agg[NN * DH];
__device__ __align__(16) float g_h[NN * DH];
__device__ __align__(16) float g_hidden[NN * 2 * DH];
__device__ int g_cnt[NN];
__device__ int g_rowptr[NN];
__device__ int g_cursor[NN];
__device__ int g_col[EE];
__device__ int g_total;
__device__ int g_is64;
// transposed fp16 weights: [N,K]. 4 slots of 32768 elements.
__device__ __align__(16) __half g_wh[4 * 32768];

// ---------------- dtype detection ----------------
__global__ void detect_dtype_kernel(const int* __restrict__ ei32, int n_words) {
    if (threadIdx.x == 0 && blockIdx.x == 0) {
        int all_zero = 1;
        for (int k = 0; k < 128; k++) {
            int idx = 2 * k + 1;
            if (idx < n_words && ei32[idx] != 0) { all_zero = 0; break; }
        }
        g_is64 = all_zero;
    }
}

// ---------------- CSR build (scan-free) ----------------
__global__ void zero_int_kernel(int* p, int n) {
    int i = blockIdx.x * blockDim.x + threadIdx.x;
    if (i < n) p[i] = 0;
    if (i == 0) g_total = 0;
}

__global__ void count_kernel(const void* __restrict__ ei, int E) {
    int e = blockIdx.x * blockDim.x + threadIdx.x;
    if (e >= E) return;
    int d;
    if (g_is64) d = (int)((const long long*)ei)[E + e];
    else        d = ((const int*)ei)[E + e];
    atomicAdd(&g_cnt[d], 1);
}

__global__ void reserve_kernel(int n) {
    int i = blockIdx.x * blockDim.x + threadIdx.x;
    if (i >= n) return;
    int c = g_cnt[i];
    int s = atomicAdd(&g_total, c);
    g_rowptr[i] = s;
    g_cursor[i] = s;
}

__global__ void fill_kernel(const void* __restrict__ ei, int E) {
    int e = blockIdx.x * blockDim.x + threadIdx.x;
    if (e >= E) return;
    int s, d;
    if (g_is64) {
        s = (int)((const long long*)ei)[e];
        d = (int)((const long long*)ei)[E + e];
    } else {
        s = ((const int*)ei)[e];
        d = ((const int*)ei)[E + e];
    }
    int pos = atomicAdd(&g_cursor[d], 1);
    g_col[pos] = s;
}

// ---------------- aggregation ----------------
__global__ void agg_kernel(const float* __restrict__ x, float* __restrict__ out, int M) {
    int node = blockIdx.x * (blockDim.x >> 5) + (threadIdx.x >> 5);
    if (node >= M) return;
    int lane = threadIdx.x & 31;
    const float4* x4 = (const float4*)x;
    float4* out4 = (float4*)out;
    size_t base = (size_t)node * 32 + lane;
    float4 acc = x4[base];
    int e = g_rowptr[node];
    int end = g_cursor[node];
    for (; e + 4 <= end; e += 4) {
        int s0 = g_col[e], s1 = g_col[e + 1], s2 = g_col[e + 2], s3 = g_col[e + 3];
        float4 v0 = __ldg(&x4[(size_t)s0 * 32 + lane]);
        float4 v1 = __ldg(&x4[(size_t)s1 * 32 + lane]);
        float4 v2 = __ldg(&x4[(size_t)s2 * 32 + lane]);
        float4 v3 = __ldg(&x4[(size_t)s3 * 32 + lane]);
        acc.x += (v0.x + v1.x) + (v2.x + v3.x);
        acc.y += (v0.y + v1.y) + (v2.y + v3.y);
        acc.z += (v0.z + v1.z) + (v2.z + v3.z);
        acc.w += (v0.w + v1.w) + (v2.w + v3.w);
    }
    for (; e < end; e++) {
        int s = g_col[e];
        float4 v = __ldg(&x4[(size_t)s * 32 + lane]);
        acc.x += v.x; acc.y += v.y; acc.z += v.z; acc.w += v.w;
    }
    out4[base] = acc;
}

// ---------------- weight transpose + fp16 convert ----------------
__global__ void conv_w_kernel(const float* __restrict__ W,
                              __half* __restrict__ out, int K, int N) {
    int i = blockIdx.x * blockDim.x + threadIdx.x;
    if (i >= N * K) return;
    int n = i / K, k = i - n * K;
    out[i] = __float2half(W[(size_t)k * N + n]);
}

#define SA 20

__device__ __forceinline__ void mma_fp16(float& c0, float& c1, float& c2, float& c3,
                                         uint32_t a0, uint32_t a1, uint32_t a2, uint32_t a3,
                                         uint32_t b0, uint32_t b1) {
    asm volatile(
        "mma.sync.aligned.m16n8k16.row.col.f32.f16.f16.f32 "
        "{%0,%1,%2,%3}, {%4,%5,%6,%7}, {%8,%9}, {%0,%1,%2,%3};"
        : "+f"(c0), "+f"(c1), "+f"(c2), "+f"(c3)
        : "r"(a0), "r"(a1), "r"(a2), "r"(a3), "r"(b0), "r"(b1));
}

// ---------------- fp16 2-pass GEMM, N=128 tile (R9 kernel, unchanged) ----------------
__global__ __launch_bounds__(256, 2) void fp16_gemm_kernel(
    const float* __restrict__ A,
    const __half* __restrict__ Wh,
    const float* __restrict__ bias,
    float* __restrict__ C,
    int M, int N, int K, int relu)
{
    __shared__ uint32_t Ah[128 * SA];
    __shared__ uint32_t Al[128 * SA];
    __shared__ uint32_t Bh[128 * SA];

    int tid = threadIdx.x;
    int wid = tid >> 5, lane = tid & 31;
    int g = lane >> 2, t4 = lane & 3;
    int warp_m = (wid >> 2) * 64;
    int warp_n = (wid & 3) * 32;
    int br = blockIdx.y * 128, bc = blockIdx.x * 128;

    int row = tid >> 1;
    int ks2 = (tid & 1) * 8;
    bool a_ok = (br + row) < M;
    const float* a_src = A + (size_t)(a_ok ? (br + row) : 0) * K + ks2 * 2;
    const __half* b_src = Wh + (size_t)(bc + row) * K + ks2 * 2;

    float acc[4][4][4];
#pragma unroll
    for (int i = 0; i < 4; i++)
#pragma unroll
        for (int j = 0; j < 4; j++)
#pragma unroll
            for (int r = 0; r < 4; r++) acc[i][j][r] = 0.0f;

    float4 f[4];
    uint4 pbh[2];
    {
        if (a_ok) {
            const float4* ap = (const float4*)a_src;
            f[0] = ap[0]; f[1] = ap[1]; f[2] = ap[2]; f[3] = ap[3];
        } else {
            f[0] = f[1] = f[2] = f[3] = make_float4(0.f, 0.f, 0.f, 0.f);
        }
        const uint4* hp = (const uint4*)b_src;
        pbh[0] = hp[0]; pbh[1] = hp[1];
    }

    for (int k0 = 0; k0 < K; k0 += 32) {
        uint32_t rb = row * SA + ks2;
#pragma unroll
        for (int j = 0; j < 4; j++) {
            float xs[4] = {f[j].x, f[j].y, f[j].z, f[j].w};
#pragma unroll
            for (int p = 0; p < 2; p++) {
                float x0 = xs[2 * p], x1 = xs[2 * p + 1];
                __half2 h = __float22half2_rn(make_float2(x0, x1));
                float l0 = x0 - __half2float(__low2half(h));
                float l1 = x1 - __half2float(__high2half(h));
                __half2 l = __float22half2_rn(make_float2(l0, l1));
                Ah[rb + 2 * j + p] = *(uint32_t*)&h;
                Al[rb + 2 * j + p] = *(uint32_t*)&l;
            }
        }
        *(uint4*)&Bh[rb] = pbh[0];
        *(uint4*)&Bh[rb + 4] = pbh[1];
        __syncthreads();

        if (k0 + 32 < K) {
            a_src += 32; b_src += 32;
            if (a_ok) {
                const float4* ap = (const float4*)a_src;
                f[0] = ap[0]; f[1] = ap[1]; f[2] = ap[2]; f[3] = ap[3];
            }
            const uint4* hp = (const uint4*)b_src;
            pbh[0] = hp[0]; pbh[1] = hp[1];
        }

#pragma unroll
        for (int s = 0; s < 2; s++) {
            int so = s * 8;
            uint32_t ah[4][4], al[4][4];
#pragma unroll
            for (int mt = 0; mt < 4; mt++) {
                int m0 = warp_m + mt * 16 + g;
                uint32_t i0 = m0 * SA + so + t4;
                uint32_t i1 = (m0 + 8) * SA + so + t4;
                ah[mt][0] = Ah[i0];     ah[mt][1] = Ah[i1];
                ah[mt][2] = Ah[i0 + 4]; ah[mt][3] = Ah[i1 + 4];
                al[mt][0] = Al[i0];     al[mt][1] = Al[i1];
                al[mt][2] = Al[i0 + 4]; al[mt][3] = Al[i1 + 4];
            }
#pragma unroll
            for (int nt = 0; nt < 4; nt++) {
                int n0 = warp_n + nt * 8 + g;
                uint32_t ib = n0 * SA + so + t4;
                uint32_t bh0 = Bh[ib], bh1 = Bh[ib + 4];
#pragma unroll
                for (int mt = 0; mt < 4; mt++) {
                    float* cc = acc[mt][nt];
                    mma_fp16(cc[0], cc[1], cc[2], cc[3],
                             ah[mt][0], ah[mt][1], ah[mt][2], ah[mt][3], bh0, bh1);
                    mma_fp16(cc[0], cc[1], cc[2], cc[3],
                             al[mt][0], al[mt][1], al[mt][2], al[mt][3], bh0, bh1);
                }
            }
        }
        __syncthreads();
    }

#pragma unroll
    for (int mt = 0; mt < 4; mt++) {
#pragma unroll
        for (int nt = 0; nt < 4; nt++) {
            int r0 = br + warp_m + mt * 16 + g;
            int cc = bc + warp_n + nt * 8 + 2 * t4;
            float2 bv = *(const float2*)&bias[cc];
            float* a = acc[mt][nt];
            if (r0 < M) {
                float2 v = make_float2(a[0] + bv.x, a[1] + bv.y);
                if (relu) { v.x = fmaxf(v.x, 0.f); v.y = fmaxf(v.y, 0.f); }
                *(float2*)&C[(size_t)r0 * N + cc] = v;
            }
            int r1 = r0 + 8;
            if (r1 < M) {
                float2 v = make_float2(a[2] + bv.x, a[3] + bv.y);
                if (relu) { v.x = fmaxf(v.x, 0.f); v.y = fmaxf(v.y, 0.f); }
                *(float2*)&C[(size_t)r1 * N + cc] = v;
            }
        }
    }
}

// ---------------- fp16 2-pass GEMM, full N=256 tile ----------------
// One CTA covers 128 rows x all 256 cols: A loaded+split once, warp tile 64x64.
// K = 128 fixed shape usage (runtime K), N = 256.
__global__ __launch_bounds__(256, 1) void fp16_gemm256_kernel(
    const float* __restrict__ A,
    const __half* __restrict__ Wh,
    const float* __restrict__ bias,
    float* __restrict__ C,
    int M, int K, int relu)
{
    const int N = 256;
    __shared__ uint32_t Ah[128 * SA];
    __shared__ uint32_t Al[128 * SA];
    __shared__ uint32_t Bh[256 * SA];

    int tid = threadIdx.x;
    int wid = tid >> 5, lane = tid & 31;
    int g = lane >> 2, t4 = lane & 3;
    int warp_m = (wid >> 2) * 64;       // 0 or 64
    int warp_n = (wid & 3) * 64;        // 0,64,128,192
    int br = blockIdx.y * 128;

    // A load: 2 threads per row, 16 k-values each
    int row = tid >> 1;
    int ks2 = (tid & 1) * 8;
    bool a_ok = (br + row) < M;
    const float* a_src = A + (size_t)(a_ok ? (br + row) : 0) * K + ks2 * 2;
    // B load: 1 thread per N-row, 32 halves (16 uints)
    const __half* b_src = Wh + (size_t)tid * K;

    float acc[4][8][4];
#pragma unroll
    for (int i = 0; i < 4; i++)
#pragma unroll
        for (int j = 0; j < 8; j++)
#pragma unroll
            for (int r = 0; r < 4; r++) acc[i][j][r] = 0.0f;

    // prefetch tile 0
    float4 f[4];
    uint4 pb[4];
    {
        if (a_ok) {
            const float4* ap = (const float4*)a_src;
            f[0] = ap[0]; f[1] = ap[1]; f[2] = ap[2]; f[3] = ap[3];
        } else {
            f[0] = f[1] = f[2] = f[3] = make_float4(0.f, 0.f, 0.f, 0.f);
        }
        const uint4* hp = (const uint4*)b_src;
        pb[0] = hp[0]; pb[1] = hp[1]; pb[2] = hp[2]; pb[3] = hp[3];
    }

    for (int k0 = 0; k0 < K; k0 += 32) {
        // staged regs -> smem
        uint32_t rb = row * SA + ks2;
#pragma unroll
        for (int j = 0; j < 4; j++) {
            float xs[4] = {f[j].x, f[j].y, f[j].z, f[j].w};
#pragma unroll
            for (int p = 0; p < 2; p++) {
                float x0 = xs[2 * p], x1 = xs[2 * p + 1];
                __half2 h = __float22half2_rn(make_float2(x0, x1));
                float l0 = x0 - __half2float(__low2half(h));
                float l1 = x1 - __half2float(__high2half(h));
                __half2 l = __float22half2_rn(make_float2(l0, l1));
                Ah[rb + 2 * j + p] = *(uint32_t*)&h;
                Al[rb + 2 * j + p] = *(uint32_t*)&l;
            }
        }
        {
            uint32_t bb = tid * SA;
            *(uint4*)&Bh[bb]      = pb[0];
            *(uint4*)&Bh[bb + 4]  = pb[1];
            *(uint4*)&Bh[bb + 8]  = pb[2];
            *(uint4*)&Bh[bb + 12] = pb[3];
        }
        __syncthreads();

        // prefetch next
        if (k0 + 32 < K) {
            a_src += 32; b_src += 32;
            if (a_ok) {
                const float4* ap = (const float4*)a_src;
                f[0] = ap[0]; f[1] = ap[1]; f[2] = ap[2]; f[3] = ap[3];
            }
            const uint4* hp = (const uint4*)b_src;
            pb[0] = hp[0]; pb[1] = hp[1]; pb[2] = hp[2]; pb[3] = hp[3];
        }

        // compute: 2 k16-slices; warp tile 64x64
#pragma unroll
        for (int s = 0; s < 2; s++) {
            int so = s * 8;
            uint32_t ah[4][4], al[4][4];
#pragma unroll
            for (int mt = 0; mt < 4; mt++) {
                int m0 = warp_m + mt * 16 + g;
                uint32_t i0 = m0 * SA + so + t4;
                uint32_t i1 = (m0 + 8) * SA + so + t4;
                ah[mt][0] = Ah[i0];     ah[mt][1] = Ah[i1];
                ah[mt][2] = Ah[i0 + 4]; ah[mt][3] = Ah[i1 + 4];
                al[mt][0] = Al[i0];     al[mt][1] = Al[i1];
                al[mt][2] = Al[i0 + 4]; al[mt][3] = Al[i1 + 4];
            }
#pragma unroll
            for (int nt = 0; nt < 8; nt++) {
                int n0 = warp_n + nt * 8 + g;
                uint32_t ib = n0 * SA + so + t4;
                uint32_t bh0 = Bh[ib], bh1 = Bh[ib + 4];
#pragma unroll
                for (int mt = 0; mt < 4; mt++) {
                    float* cc = acc[mt][nt];
                    mma_fp16(cc[0], cc[1], cc[2], cc[3],
                             ah[mt][0], ah[mt][1], ah[mt][2], ah[mt][3], bh0, bh1);
                    mma_fp16(cc[0], cc[1], cc[2], cc[3],
                             al[mt][0], al[mt][1], al[mt][2], al[mt][3], bh0, bh1);
                }
            }
        }
        __syncthreads();
    }

    // epilogue
#pragma unroll
    for (int mt = 0; mt < 4; mt++) {
#pragma unroll
        for (int nt = 0; nt < 8; nt++) {
            int r0 = br + warp_m + mt * 16 + g;
            int cc = warp_n + nt * 8 + 2 * t4;
            float2 bv = *(const float2*)&bias[cc];
            float* a = acc[mt][nt];
            if (r0 < M) {
                float2 v = make_float2(a[0] + bv.x, a[1] + bv.y);
                if (relu) { v.x = fmaxf(v.x, 0.f); v.y = fmaxf(v.y, 0.f); }
                *(float2*)&C[(size_t)r0 * N + cc] = v;
            }
            int r1 = r0 + 8;
            if (r1 < M) {
                float2 v = make_float2(a[2] + bv.x, a[3] + bv.y);
                if (relu) { v.x = fmaxf(v.x, 0.f); v.y = fmaxf(v.y, 0.f); }
                *(float2*)&C[(size_t)r1 * N + cc] = v;
            }
        }
    }
}

// ---------------- classifier ----------------
__global__ __launch_bounds__(256) void fc40_kernel(
    const float* __restrict__ A, const float* __restrict__ W,
    const float* __restrict__ bias, float* __restrict__ out, int M)
{
    __shared__ float Ws[DH * NCLS];
    for (int i = threadIdx.x; i < DH * NCLS; i += blockDim.x) Ws[i] = W[i];
    __syncthreads();

    int row = blockIdx.x * blockDim.x + threadIdx.x;
    if (row >= M) return;

    float acc[NCLS];
#pragma unroll
    for (int j = 0; j < NCLS; j++) acc[j] = bias[j];

    const float4* __restrict__ a4 = (const float4*)(A + (size_t)row * DH);
#pragma unroll 8
    for (int kc = 0; kc < DH / 4; kc++) {
        float4 av = a4[kc];
        int k = kc * 4;
        const float* w0 = &Ws[(k + 0) * NCLS];
        const float* w1 = &Ws[(k + 1) * NCLS];
        const float* w2 = &Ws[(k + 2) * NCLS];
        const float* w3 = &Ws[(k + 3) * NCLS];
#pragma unroll
        for (int j = 0; j < NCLS; j++)
            acc[j] += av.x * w0[j] + av.y * w1[j] + av.z * w2[j] + av.w * w3[j];
    }
    float* o = out + (size_t)row * NCLS;
#pragma unroll
    for (int j = 0; j < NCLS; j++) o[j] = acc[j];
}

// ---------------- launch ----------------
extern "C" void kernel_launch(void* const* d_in, const int* in_sizes, int n_in,
                              void* d_out, int out_size)
{
    const float* x    = (const float*)d_in[0];
    const void*  ei   = d_in[1];
    const float* W11  = (const float*)d_in[2];
    const float* b11  = (const float*)d_in[3];
    const float* W12  = (const float*)d_in[4];
    const float* b12  = (const float*)d_in[5];
    const float* W21  = (const float*)d_in[6];
    const float* b21  = (const float*)d_in[7];
    const float* W22  = (const float*)d_in[8];
    const float* b22  = (const float*)d_in[9];
    const float* Wfc  = (const float*)d_in[10];
    const float* bfc  = (const float*)d_in[11];

    int M = in_sizes[0] / DH;      // 50000
    int E = in_sizes[1] / 2;       // 800000

    float *p_agg, *p_h, *p_hidden;
    cudaGetSymbolAddress((void**)&p_agg, g_agg);
    cudaGetSymbolAddress((void**)&p_h, g_h);
    cudaGetSymbolAddress((void**)&p_hidden, g_hidden);
    int* p_cnt;
    cudaGetSymbolAddress((void**)&p_cnt, g_cnt);
    __half* p_wh;
    cudaGetSymbolAddress((void**)&p_wh, g_wh);

    detect_dtype_kernel<<<1, 32>>>((const int*)ei, 2 * E);

    // CSR build
    zero_int_kernel<<<(M + 255) / 256, 256>>>(p_cnt, M);
    count_kernel<<<(E + 255) / 256, 256>>>(ei, E);
    reserve_kernel<<<(M + 255) / 256, 256>>>(M);
    fill_kernel<<<(E + 255) / 256, 256>>>(ei, E);

    // weight transpose + fp16 convert
    const int WS = 32768;
    conv_w_kernel<<<WS / 256, 256>>>(W11, p_wh + 0 * WS, 128, 256);
    conv_w_kernel<<<WS / 256, 256>>>(W12, p_wh + 1 * WS, 256, 128);
    conv_w_kernel<<<WS / 256, 256>>>(W21, p_wh + 2 * WS, 128, 256);
    conv_w_kernel<<<WS / 256, 256>>>(W22, p_wh + 3 * WS, 256, 128);

    int agg_blocks = (M + 7) / 8;
    dim3 g1(1, (M + 127) / 128);   // N=256 full-width tiles
    dim3 g2(1, (M + 127) / 128);   // N=128

    // Layer 1
    agg_kernel<<<agg_blocks, 256>>>(x, p_agg, M);
    fp16_gemm256_kernel<<<g1, 256>>>(p_agg, p_wh + 0 * WS, b11, p_hidden, M, 128, 1);
    fp16_gemm_kernel<<<g2, 256>>>(p_hidden, p_wh + 1 * WS, b12, p_h, M, 128, 256, 1);

    // Layer 2
    agg_kernel<<<agg_blocks, 256>>>(p_h, p_agg, M);
    fp16_gemm256_kernel<<<g1, 256>>>(p_agg, p_wh + 2 * WS, b21, p_hidden, M, 128, 1);
    fp16_gemm_kernel<<<g2, 256>>>(p_hidden, p_wh + 3 * WS, b22, p_h, M, 128, 256, 1);

    // Classifier
    fc40_kernel<<<(M + 255) / 256, 256>>>(p_h, Wfc, bfc, (float*)d_out, M);
}

// round 11
// speedup vs baseline: 2.0239x; 1.0227x over previous
#include <cuda_runtime.h>
#include <cuda_bf16.h>
#include <cuda_fp16.h>
#include <cstdint>

#define NN 50000
#define EE 800000
#define DH 128
#define NCLS 40

// ---------------- scratch ----------------
__device__ __align__(16) float g_agg[NN * DH];
__device__ __align__(16) float g_h[NN * DH];
__device__ __align__(16) float g_hidden[NN * 2 * DH];
__device__ int g_cnt[NN];
__device__ int g_rowptr[NN];
__device__ int g_cursor[NN];
__device__ int g_col[EE];
__device__ int g_total;
__device__ int g_is64;
// transposed fp16 weights: [N,K]. 4 slots of 32768 elements.
__device__ __align__(16) __half g_wh[4 * 32768];

// ---------------- dtype detection ----------------
__global__ void detect_dtype_kernel(const int* __restrict__ ei32, int n_words) {
    if (threadIdx.x == 0 && blockIdx.x == 0) {
        int all_zero = 1;
        for (int k = 0; k < 128; k++) {
            int idx = 2 * k + 1;
            if (idx < n_words && ei32[idx] != 0) { all_zero = 0; break; }
        }
        g_is64 = all_zero;
    }
}

// ---------------- CSR build (scan-free) ----------------
__global__ void zero_int_kernel(int* p, int n) {
    int i = blockIdx.x * blockDim.x + threadIdx.x;
    if (i < n) p[i] = 0;
    if (i == 0) g_total = 0;
}

__global__ void count_kernel(const void* __restrict__ ei, int E) {
    int e = blockIdx.x * blockDim.x + threadIdx.x;
    if (e >= E) return;
    int d;
    if (g_is64) d = (int)((const long long*)ei)[E + e];
    else        d = ((const int*)ei)[E + e];
    atomicAdd(&g_cnt[d], 1);
}

__global__ void reserve_kernel(int n) {
    int i = blockIdx.x * blockDim.x + threadIdx.x;
    if (i >= n) return;
    int c = g_cnt[i];
    int s = atomicAdd(&g_total, c);
    g_rowptr[i] = s;
    g_cursor[i] = s;
}

__global__ void fill_kernel(const void* __restrict__ ei, int E) {
    int e = blockIdx.x * blockDim.x + threadIdx.x;
    if (e >= E) return;
    int s, d;
    if (g_is64) {
        s = (int)((const long long*)ei)[e];
        d = (int)((const long long*)ei)[E + e];
    } else {
        s = ((const int*)ei)[e];
        d = ((const int*)ei)[E + e];
    }
    int pos = atomicAdd(&g_cursor[d], 1);
    g_col[pos] = s;
}

// ---------------- aggregation ----------------
__global__ void agg_kernel(const float* __restrict__ x, float* __restrict__ out, int M) {
    int node = blockIdx.x * (blockDim.x >> 5) + (threadIdx.x >> 5);
    if (node >= M) return;
    int lane = threadIdx.x & 31;
    const float4* x4 = (const float4*)x;
    float4* out4 = (float4*)out;
    size_t base = (size_t)node * 32 + lane;
    float4 acc = x4[base];
    int e = g_rowptr[node];
    int end = g_cursor[node];
    for (; e + 4 <= end; e += 4) {
        int s0 = g_col[e], s1 = g_col[e + 1], s2 = g_col[e + 2], s3 = g_col[e + 3];
        float4 v0 = __ldg(&x4[(size_t)s0 * 32 + lane]);
        float4 v1 = __ldg(&x4[(size_t)s1 * 32 + lane]);
        float4 v2 = __ldg(&x4[(size_t)s2 * 32 + lane]);
        float4 v3 = __ldg(&x4[(size_t)s3 * 32 + lane]);
        acc.x += (v0.x + v1.x) + (v2.x + v3.x);
        acc.y += (v0.y + v1.y) + (v2.y + v3.y);
        acc.z += (v0.z + v1.z) + (v2.z + v3.z);
        acc.w += (v0.w + v1.w) + (v2.w + v3.w);
    }
    for (; e < end; e++) {
        int s = g_col[e];
        float4 v = __ldg(&x4[(size_t)s * 32 + lane]);
        acc.x += v.x; acc.y += v.y; acc.z += v.z; acc.w += v.w;
    }
    out4[base] = acc;
}

// ---------------- weight transpose + fp16 convert ----------------
__global__ void conv_w_kernel(const float* __restrict__ W,
                              __half* __restrict__ out, int K, int N) {
    int i = blockIdx.x * blockDim.x + threadIdx.x;
    if (i >= N * K) return;
    int n = i / K, k = i - n * K;
    out[i] = __float2half(W[(size_t)k * N + n]);
}

#define SA 20

__device__ __forceinline__ void mma_fp16(float& c0, float& c1, float& c2, float& c3,
                                         uint32_t a0, uint32_t a1, uint32_t a2, uint32_t a3,
                                         uint32_t b0, uint32_t b1) {
    asm volatile(
        "mma.sync.aligned.m16n8k16.row.col.f32.f16.f16.f32 "
        "{%0,%1,%2,%3}, {%4,%5,%6,%7}, {%8,%9}, {%0,%1,%2,%3};"
        : "+f"(c0), "+f"(c1), "+f"(c2), "+f"(c3)
        : "r"(a0), "r"(a1), "r"(a2), "r"(a3), "r"(b0), "r"(b1));
}

__device__ __forceinline__ void ldsm_x4(uint32_t& r0, uint32_t& r1, uint32_t& r2, uint32_t& r3,
                                        uint32_t addr) {
    asm volatile("ldmatrix.sync.aligned.m8n8.x4.shared.b16 {%0,%1,%2,%3}, [%4];"
                 : "=r"(r0), "=r"(r1), "=r"(r2), "=r"(r3) : "r"(addr));
}
__device__ __forceinline__ void ldsm_x2(uint32_t& r0, uint32_t& r1, uint32_t addr) {
    asm volatile("ldmatrix.sync.aligned.m8n8.x2.shared.b16 {%0,%1}, [%2];"
                 : "=r"(r0), "=r"(r1) : "r"(addr));
}
__device__ __forceinline__ uint32_t smem_addr(const void* p) {
    return (uint32_t)__cvta_generic_to_shared(p);
}

// ---------------- fp16 2-pass GEMM, N=128 tile ----------------
__global__ __launch_bounds__(256, 2) void fp16_gemm_kernel(
    const float* __restrict__ A,
    const __half* __restrict__ Wh,
    const float* __restrict__ bias,
    float* __restrict__ C,
    int M, int N, int K, int relu)
{
    __shared__ uint32_t Ah[128 * SA];
    __shared__ uint32_t Al[128 * SA];
    __shared__ uint32_t Bh[128 * SA];

    int tid = threadIdx.x;
    int wid = tid >> 5, lane = tid & 31;
    int g = lane >> 2, t4 = lane & 3;
    int warp_m = (wid >> 2) * 64;
    int warp_n = (wid & 3) * 32;
    int br = blockIdx.y * 128, bc = blockIdx.x * 128;

    int row = tid >> 1;
    int ks2 = (tid & 1) * 8;
    bool a_ok = (br + row) < M;
    const float* a_src = A + (size_t)(a_ok ? (br + row) : 0) * K + ks2 * 2;
    const __half* b_src = Wh + (size_t)(bc + row) * K + ks2 * 2;

    // ldmatrix lane-address components (bytes)
    uint32_t AhB = smem_addr(Ah), AlB = smem_addr(Al), BhB = smem_addr(Bh);
    uint32_t laneA = ((lane & 15) * SA + (lane >> 4) * 4) * 4;
    uint32_t laneB = ((lane & 7) * SA + ((lane >> 3) & 1) * 4) * 4;

    float acc[4][4][4];
#pragma unroll
    for (int i = 0; i < 4; i++)
#pragma unroll
        for (int j = 0; j < 4; j++)
#pragma unroll
            for (int r = 0; r < 4; r++) acc[i][j][r] = 0.0f;

    float4 f[4];
    uint4 pbh[2];
    {
        if (a_ok) {
            const float4* ap = (const float4*)a_src;
            f[0] = ap[0]; f[1] = ap[1]; f[2] = ap[2]; f[3] = ap[3];
        } else {
            f[0] = f[1] = f[2] = f[3] = make_float4(0.f, 0.f, 0.f, 0.f);
        }
        const uint4* hp = (const uint4*)b_src;
        pbh[0] = hp[0]; pbh[1] = hp[1];
    }

    for (int k0 = 0; k0 < K; k0 += 32) {
        uint32_t rb = row * SA + ks2;
#pragma unroll
        for (int j = 0; j < 4; j++) {
            float xs[4] = {f[j].x, f[j].y, f[j].z, f[j].w};
#pragma unroll
            for (int p = 0; p < 2; p++) {
                float x0 = xs[2 * p], x1 = xs[2 * p + 1];
                __half2 h = __float22half2_rn(make_float2(x0, x1));
                float l0 = x0 - __half2float(__low2half(h));
                float l1 = x1 - __half2float(__high2half(h));
                __half2 l = __float22half2_rn(make_float2(l0, l1));
                Ah[rb + 2 * j + p] = *(uint32_t*)&h;
                Al[rb + 2 * j + p] = *(uint32_t*)&l;
            }
        }
        *(uint4*)&Bh[rb] = pbh[0];
        *(uint4*)&Bh[rb + 4] = pbh[1];
        __syncthreads();

        if (k0 + 32 < K) {
            a_src += 32; b_src += 32;
            if (a_ok) {
                const float4* ap = (const float4*)a_src;
                f[0] = ap[0]; f[1] = ap[1]; f[2] = ap[2]; f[3] = ap[3];
            }
            const uint4* hp = (const uint4*)b_src;
            pbh[0] = hp[0]; pbh[1] = hp[1];
        }

#pragma unroll
        for (int s = 0; s < 2; s++) {
            int so = s * 8;
            uint32_t ah[4][4], al[4][4];
#pragma unroll
            for (int mt = 0; mt < 4; mt++) {
                uint32_t off = (uint32_t)(((warp_m + mt * 16) * SA + so) * 4);
                ldsm_x4(ah[mt][0], ah[mt][1], ah[mt][2], ah[mt][3], AhB + off + laneA);
                ldsm_x4(al[mt][0], al[mt][1], al[mt][2], al[mt][3], AlB + off + laneA);
            }
#pragma unroll
            for (int nt = 0; nt < 4; nt++) {
                uint32_t boff = (uint32_t)(((warp_n + nt * 8) * SA + so) * 4);
                uint32_t bh0, bh1;
                ldsm_x2(bh0, bh1, BhB + boff + laneB);
#pragma unroll
                for (int mt = 0; mt < 4; mt++) {
                    float* cc = acc[mt][nt];
                    mma_fp16(cc[0], cc[1], cc[2], cc[3],
                             ah[mt][0], ah[mt][1], ah[mt][2], ah[mt][3], bh0, bh1);
                    mma_fp16(cc[0], cc[1], cc[2], cc[3],
                             al[mt][0], al[mt][1], al[mt][2], al[mt][3], bh0, bh1);
                }
            }
        }
        __syncthreads();
    }

#pragma unroll
    for (int mt = 0; mt < 4; mt++) {
#pragma unroll
        for (int nt = 0; nt < 4; nt++) {
            int r0 = br + warp_m + mt * 16 + g;
            int cc = bc + warp_n + nt * 8 + 2 * t4;
            float2 bv = *(const float2*)&bias[cc];
            float* a = acc[mt][nt];
            if (r0 < M) {
                float2 v = make_float2(a[0] + bv.x, a[1] + bv.y);
                if (relu) { v.x = fmaxf(v.x, 0.f); v.y = fmaxf(v.y, 0.f); }
                *(float2*)&C[(size_t)r0 * N + cc] = v;
            }
            int r1 = r0 + 8;
            if (r1 < M) {
                float2 v = make_float2(a[2] + bv.x, a[3] + bv.y);
                if (relu) { v.x = fmaxf(v.x, 0.f); v.y = fmaxf(v.y, 0.f); }
                *(float2*)&C[(size_t)r1 * N + cc] = v;
            }
        }
    }
}

// ---------------- fp16 2-pass GEMM, full N=256 tile ----------------
__global__ __launch_bounds__(256, 1) void fp16_gemm256_kernel(
    const float* __restrict__ A,
    const __half* __restrict__ Wh,
    const float* __restrict__ bias,
    float* __restrict__ C,
    int M, int K, int relu)
{
    const int N = 256;
    __shared__ uint32_t Ah[128 * SA];
    __shared__ uint32_t Al[128 * SA];
    __shared__ uint32_t Bh[256 * SA];

    int tid = threadIdx.x;
    int wid = tid >> 5, lane = tid & 31;
    int g = lane >> 2, t4 = lane & 3;
    int warp_m = (wid >> 2) * 64;
    int warp_n = (wid & 3) * 64;
    int br = blockIdx.y * 128;

    int row = tid >> 1;
    int ks2 = (tid & 1) * 8;
    bool a_ok = (br + row) < M;
    const float* a_src = A + (size_t)(a_ok ? (br + row) : 0) * K + ks2 * 2;
    const __half* b_src = Wh + (size_t)tid * K;

    uint32_t AhB = smem_addr(Ah), AlB = smem_addr(Al), BhB = smem_addr(Bh);
    uint32_t laneA = ((lane & 15) * SA + (lane >> 4) * 4) * 4;
    uint32_t laneB = ((lane & 7) * SA + ((lane >> 3) & 1) * 4) * 4;

    float acc[4][8][4];
#pragma unroll
    for (int i = 0; i < 4; i++)
#pragma unroll
        for (int j = 0; j < 8; j++)
#pragma unroll
            for (int r = 0; r < 4; r++) acc[i][j][r] = 0.0f;

    float4 f[4];
    uint4 pb[4];
    {
        if (a_ok) {
            const float4* ap = (const float4*)a_src;
            f[0] = ap[0]; f[1] = ap[1]; f[2] = ap[2]; f[3] = ap[3];
        } else {
            f[0] = f[1] = f[2] = f[3] = make_float4(0.f, 0.f, 0.f, 0.f);
        }
        const uint4* hp = (const uint4*)b_src;
        pb[0] = hp[0]; pb[1] = hp[1]; pb[2] = hp[2]; pb[3] = hp[3];
    }

    for (int k0 = 0; k0 < K; k0 += 32) {
        uint32_t rb = row * SA + ks2;
#pragma unroll
        for (int j = 0; j < 4; j++) {
            float xs[4] = {f[j].x, f[j].y, f[j].z, f[j].w};
#pragma unroll
            for (int p = 0; p < 2; p++) {
                float x0 = xs[2 * p], x1 = xs[2 * p + 1];
                __half2 h = __float22half2_rn(make_float2(x0, x1));
                float l0 = x0 - __half2float(__low2half(h));
                float l1 = x1 - __half2float(__high2half(h));
                __half2 l = __float22half2_rn(make_float2(l0, l1));
                Ah[rb + 2 * j + p] = *(uint32_t*)&h;
                Al[rb + 2 * j + p] = *(uint32_t*)&l;
            }
        }
        {
            uint32_t bb = tid * SA;
            *(uint4*)&Bh[bb]      = pb[0];
            *(uint4*)&Bh[bb + 4]  = pb[1];
            *(uint4*)&Bh[bb + 8]  = pb[2];
            *(uint4*)&Bh[bb + 12] = pb[3];
        }
        __syncthreads();

        if (k0 + 32 < K) {
            a_src += 32; b_src += 32;
            if (a_ok) {
                const float4* ap = (const float4*)a_src;
                f[0] = ap[0]; f[1] = ap[1]; f[2] = ap[2]; f[3] = ap[3];
            }
            const uint4* hp = (const uint4*)b_src;
            pb[0] = hp[0]; pb[1] = hp[1]; pb[2] = hp[2]; pb[3] = hp[3];
        }

#pragma unroll
        for (int s = 0; s < 2; s++) {
            int so = s * 8;
            uint32_t ah[4][4], al[4][4];
#pragma unroll
            for (int mt = 0; mt < 4; mt++) {
                uint32_t off = (uint32_t)(((warp_m + mt * 16) * SA + so) * 4);
                ldsm_x4(ah[mt][0], ah[mt][1], ah[mt][2], ah[mt][3], AhB + off + laneA);
                ldsm_x4(al[mt][0], al[mt][1], al[mt][2], al[mt][3], AlB + off + laneA);
            }
#pragma unroll
            for (int nt = 0; nt < 8; nt++) {
                uint32_t boff = (uint32_t)(((warp_n + nt * 8) * SA + so) * 4);
                uint32_t bh0, bh1;
                ldsm_x2(bh0, bh1, BhB + boff + laneB);
#pragma unroll
                for (int mt = 0; mt < 4; mt++) {
                    float* cc = acc[mt][nt];
                    mma_fp16(cc[0], cc[1], cc[2], cc[3],
                             ah[mt][0], ah[mt][1], ah[mt][2], ah[mt][3], bh0, bh1);
                    mma_fp16(cc[0], cc[1], cc[2], cc[3],
                             al[mt][0], al[mt][1], al[mt][2], al[mt][3], bh0, bh1);
                }
            }
        }
        __syncthreads();
    }

#pragma unroll
    for (int mt = 0; mt < 4; mt++) {
#pragma unroll
        for (int nt = 0; nt < 8; nt++) {
            int r0 = br + warp_m + mt * 16 + g;
            int cc = warp_n + nt * 8 + 2 * t4;
            float2 bv = *(const float2*)&bias[cc];
            float* a = acc[mt][nt];
            if (r0 < M) {
                float2 v = make_float2(a[0] + bv.x, a[1] + bv.y);
                if (relu) { v.x = fmaxf(v.x, 0.f); v.y = fmaxf(v.y, 0.f); }
                *(float2*)&C[(size_t)r0 * N + cc] = v;
            }
            int r1 = r0 + 8;
            if (r1 < M) {
                float2 v = make_float2(a[2] + bv.x, a[3] + bv.y);
                if (relu) { v.x = fmaxf(v.x, 0.f); v.y = fmaxf(v.y, 0.f); }
                *(float2*)&C[(size_t)r1 * N + cc] = v;
            }
        }
    }
}

// ---------------- classifier ----------------
__global__ __launch_bounds__(256) void fc40_kernel(
    const float* __restrict__ A, const float* __restrict__ W,
    const float* __restrict__ bias, float* __restrict__ out, int M)
{
    __shared__ float Ws[DH * NCLS];
    for (int i = threadIdx.x; i < DH * NCLS; i += blockDim.x) Ws[i] = W[i];
    __syncthreads();

    int row = blockIdx.x * blockDim.x + threadIdx.x;
    if (row >= M) return;

    float acc[NCLS];
#pragma unroll
    for (int j = 0; j < NCLS; j++) acc[j] = bias[j];

    const float4* __restrict__ a4 = (const float4*)(A + (size_t)row * DH);
#pragma unroll 8
    for (int kc = 0; kc < DH / 4; kc++) {
        float4 av = a4[kc];
        int k = kc * 4;
        const float* w0 = &Ws[(k + 0) * NCLS];
        const float* w1 = &Ws[(k + 1) * NCLS];
        const float* w2 = &Ws[(k + 2) * NCLS];
        const float* w3 = &Ws[(k + 3) * NCLS];
#pragma unroll
        for (int j = 0; j < NCLS; j++)
            acc[j] += av.x * w0[j] + av.y * w1[j] + av.z * w2[j] + av.w * w3[j];
    }
    float* o = out + (size_t)row * NCLS;
#pragma unroll
    for (int j = 0; j < NCLS; j++) o[j] = acc[j];
}

// ---------------- launch ----------------
extern "C" void kernel_launch(void* const* d_in, const int* in_sizes, int n_in,
                              void* d_out, int out_size)
{
    const float* x    = (const float*)d_in[0];
    const void*  ei   = d_in[1];
    const float* W11  = (const float*)d_in[2];
    const float* b11  = (const float*)d_in[3];
    const float* W12  = (const float*)d_in[4];
    const float* b12  = (const float*)d_in[5];
    const float* W21  = (const float*)d_in[6];
    const float* b21  = (const float*)d_in[7];
    const float* W22  = (const float*)d_in[8];
    const float* b22  = (const float*)d_in[9];
    const float* Wfc  = (const float*)d_in[10];
    const float* bfc  = (const float*)d_in[11];

    int M = in_sizes[0] / DH;      // 50000
    int E = in_sizes[1] / 2;       // 800000

    float *p_agg, *p_h, *p_hidden;
    cudaGetSymbolAddress((void**)&p_agg, g_agg);
    cudaGetSymbolAddress((void**)&p_h, g_h);
    cudaGetSymbolAddress((void**)&p_hidden, g_hidden);
    int* p_cnt;
    cudaGetSymbolAddress((void**)&p_cnt, g_cnt);
    __half* p_wh;
    cudaGetSymbolAddress((void**)&p_wh, g_wh);

    detect_dtype_kernel<<<1, 32>>>((const int*)ei, 2 * E);

    // CSR build
    zero_int_kernel<<<(M + 255) / 256, 256>>>(p_cnt, M);
    count_kernel<<<(E + 255) / 256, 256>>>(ei, E);
    reserve_kernel<<<(M + 255) / 256, 256>>>(M);
    fill_kernel<<<(E + 255) / 256, 256>>>(ei, E);

    // weight transpose + fp16 convert
    const int WS = 32768;
    conv_w_kernel<<<WS / 256, 256>>>(W11, p_wh + 0 * WS, 128, 256);
    conv_w_kernel<<<WS / 256, 256>>>(W12, p_wh + 1 * WS, 256, 128);
    conv_w_kernel<<<WS / 256, 256>>>(W21, p_wh + 2 * WS, 128, 256);
    conv_w_kernel<<<WS / 256, 256>>>(W22, p_wh + 3 * WS, 256, 128);

    int agg_blocks = (M + 7) / 8;
    dim3 g1(1, (M + 127) / 128);   // N=256 full-width tiles
    dim3 g2(1, (M + 127) / 128);   // N=128

    // Layer 1
    agg_kernel<<<agg_blocks, 256>>>(x, p_agg, M);
    fp16_gemm256_kernel<<<g1, 256>>>(p_agg, p_wh + 0 * WS, b11, p_hidden, M, 128, 1);
    fp16_gemm_kernel<<<g2, 256>>>(p_hidden, p_wh + 1 * WS, b12, p_h, M, 128, 256, 1);

    // Layer 2
    agg_kernel<<<agg_blocks, 256>>>(p_h, p_agg, M);
    fp16_gemm256_kernel<<<g1, 256>>>(p_agg, p_wh + 2 * WS, b21, p_hidden, M, 128, 1);
    fp16_gemm_kernel<<<g2, 256>>>(p_hidden, p_wh + 3 * WS, b22, p_h, M, 128, 256, 1);

    // Classifier
    fc40_kernel<<<(M + 255) / 256, 256>>>(p_h, Wfc, bfc, (float*)d_out, M);
}